// round 8
// baseline (speedup 1.0000x reference)
#include <cuda_runtime.h>
#include <math.h>

constexpr int kN   = 50000;
constexpr int kE   = 800000;
constexpr int kG   = 512;
constexpr int kD   = 128;
constexpr int kEE  = 64;
constexpr int kL   = 4;
constexpr int kNC  = 10;
constexpr int kSB  = (kN + 1023) / 1024;
constexpr float kBNS = 0.9999950000374997f;  // (1+1e-5)^-0.5

// grid split constants
constexpr int kEncB  = (kN * kD + 255) / 256;    // 25000 node_encode blocks
constexpr int kCntB  = (kE * 8 + 255) / 256;     // 25000 count/lraw blocks
constexpr int kXlrB  = ((kN + 63) / 64) * 2;     // 1564 xlr blocks
constexpr int kScatB = (kE + 255) / 256;         // 3125 scatter blocks

typedef unsigned long long u64;

// ---------------- f32x2 packed helpers -------------------------------------
__device__ __forceinline__ u64 pack2(float lo, float hi) {
    u64 r; asm("mov.b64 %0,{%1,%2};" : "=l"(r) : "f"(lo), "f"(hi)); return r;
}
__device__ __forceinline__ u64 splat2(float v) { return pack2(v, v); }
__device__ __forceinline__ void unpack2(u64 p, float& lo, float& hi) {
    asm("mov.b64 {%0,%1},%2;" : "=f"(lo), "=f"(hi) : "l"(p));
}
__device__ __forceinline__ u64 fma2(u64 a, u64 b, u64 c) {
    u64 r; asm("fma.rn.f32x2 %0,%1,%2,%3;" : "=l"(r) : "l"(a), "l"(b), "l"(c)); return r;
}
__device__ __forceinline__ u64 add2(u64 a, u64 b) {
    u64 r; asm("add.rn.f32x2 %0,%1,%2;" : "=l"(r) : "l"(a), "l"(b)); return r;
}

// ---------------- scratch ----------------------------------------------------
// g_deg, g_cur, g_lraw rely on zero-init at module load; a cleanup kernel at
// the end of every kernel_launch restores them to zero for the next call.
__device__ float g_x[kN * kD];
__device__ float g_xl[kN * kD];
__device__ float g_xr[kN * kD];
__device__ float g_lraw[kN * 8];      // SUM of incoming raw attrs (div by deg later)
__device__ int   g_deg[kN];
__device__ int   g_cur[kN];
__device__ int   g_off[kN + 1];
__device__ int   g_csrc[kE];
__device__ float g_eraw[(size_t)kE * 8];
__device__ float g_M[kL * 8 * kD];
__device__ float g_bep[kL * kD];
__device__ float g_gsum[kG * kD];

// ---------------- k1: node_encode + degree/lraw atomics + make_M ------------
__global__ void mega_prep(const int* __restrict__ xn, const float* __restrict__ emb,
                          const int* __restrict__ src, const int* __restrict__ dst,
                          const float* __restrict__ eattr,
                          const float* __restrict__ eW, const float* __restrict__ eb,
                          const float* __restrict__ We) {
    int b = blockIdx.x;
    if (b < kEncB) {
        int t = b * 256 + threadIdx.x;
        if (t < kN * kD) {
            int n = t >> 7, j = t & 127;
            g_x[t] = emb[xn[n] * kD + j];
        }
    } else if (b < kEncB + kCntB) {
        int t = (b - kEncB) * 256 + threadIdx.x;
        if (t < kE * 8) {
            int e = t >> 3, j = t & 7;
            int s = src[e], d = dst[e];
            if (s != d) {
                atomicAdd(&g_lraw[d * 8 + j], eattr[t]);
                if (j == 0) atomicAdd(&g_deg[d], 1);
            }
        }
    } else {
        int layer = b - kEncB - kCntB;
        const float* w = We + (size_t)layer * kEE * kD;
        for (int r = threadIdx.x; r < 8 * kD; r += 256) {
            int k = r >> 7, j = r & 127;
            float acc = 0.f;
#pragma unroll 8
            for (int u = 0; u < kEE; u++) acc += eW[k * kEE + u] * w[u * kD + j];
            g_M[layer * 8 * kD + r] = acc;
        }
        if (threadIdx.x < kD) {
            float bb = 0.f;
#pragma unroll 8
            for (int u = 0; u < kEE; u++) bb += eb[u] * w[u * kD + threadIdx.x];
            g_bep[layer * kD + threadIdx.x] = bb;
        }
    }
}

// ---------------- k2: single-block shuffle scan ------------------------------
__global__ void scan_single() {
    __shared__ int wtot[32];
    __shared__ int carrysh;
    int t = threadIdx.x, lane = t & 31, w = t >> 5;
    if (t == 0) carrysh = 0;
    __syncthreads();
    for (int c = 0; c < kSB; c++) {
        int n = c * 1024 + t;
        int v = (n < kN) ? g_deg[n] : 0;
        int inc = v;
#pragma unroll
        for (int o = 1; o < 32; o <<= 1) {
            int x = __shfl_up_sync(0xffffffffu, inc, o);
            if (lane >= o) inc += x;
        }
        if (lane == 31) wtot[w] = inc;
        __syncthreads();
        if (w == 0) {
            int wi = wtot[lane];
#pragma unroll
            for (int o = 1; o < 32; o <<= 1) {
                int y = __shfl_up_sync(0xffffffffu, wi, o);
                if (lane >= o) wi += y;
            }
            wtot[lane] = wi;
        }
        __syncthreads();
        int base = carrysh + (w ? wtot[w - 1] : 0);
        if (n < kN) g_off[n] = base + inc - v;
        __syncthreads();
        if (t == 0) carrysh += wtot[31];
        __syncthreads();
    }
    if (t == 0) g_off[kN] = carrysh;
}

// ---------------- xlr GEMM body ----------------------------------------------
__device__ __forceinline__ void xlr_body(const float* __restrict__ W,
                                         const float* __restrict__ bias,
                                         float* __restrict__ out, int n0,
                                         float* ws, float* xs /* [32][68] */) {
    int t = threadIdx.x;
    int lane = t & 31;
    int w = t >> 5;
    u64 acc[8][2] = {};
    for (int kt = 0; kt < kD; kt += 32) {
#pragma unroll
        for (int r = t; r < 32 * 128; r += 256)
            ws[r] = W[(kt + (r >> 7)) * kD + (r & 127)];
#pragma unroll
        for (int r = t; r < 64 * 32; r += 256) {
            int n = r >> 5, kk = r & 31;
            int nn = n0 + n;
            xs[kk * 68 + n] = (nn < kN) ? g_x[nn * kD + kt + kk] : 0.f;
        }
        __syncthreads();
#pragma unroll
        for (int kk = 0; kk < 32; kk++) {
            ulonglong2 wv = *(const ulonglong2*)&ws[kk * 128 + lane * 4];
            float4 xv0 = *(const float4*)&xs[kk * 68 + w * 8];
            float4 xv1 = *(const float4*)&xs[kk * 68 + w * 8 + 4];
            float xm[8] = {xv0.x, xv0.y, xv0.z, xv0.w, xv1.x, xv1.y, xv1.z, xv1.w};
#pragma unroll
            for (int m = 0; m < 8; m++) {
                u64 xp = splat2(xm[m]);
                acc[m][0] = fma2(xp, wv.x, acc[m][0]);
                acc[m][1] = fma2(xp, wv.y, acc[m][1]);
            }
        }
        __syncthreads();
    }
    float4 bv = *(const float4*)(bias + lane * 4);
#pragma unroll
    for (int m = 0; m < 8; m++) {
        int n = n0 + w * 8 + m;
        if (n < kN) {
            float a0, a1, a2, a3;
            unpack2(acc[m][0], a0, a1);
            unpack2(acc[m][1], a2, a3);
            float4 o = make_float4(a0 + bv.x, a1 + bv.y, a2 + bv.z, a3 + bv.w);
            *(float4*)&out[n * kD + lane * 4] = o;
        }
    }
}

// ---------------- k3: xlr layer0 + scatter_csr (grid split) -----------------
__global__ __launch_bounds__(256) void xlr_scatter(
        const float* __restrict__ Wl, const float* __restrict__ bl,
        const float* __restrict__ Wr, const float* __restrict__ br,
        const int* __restrict__ src, const int* __restrict__ dst,
        const float* __restrict__ eattr) {
    __shared__ __align__(16) float ws[32 * 128];
    __shared__ __align__(16) float xs[32 * 68];
    int b = blockIdx.x;
    if (b < kXlrB) {
        int half = b / (kXlrB / 2);
        int bx = b % (kXlrB / 2);
        const float* W = (half == 0 ? Wl : Wr);
        const float* bias = (half == 0 ? bl : br);
        float* out = half == 0 ? g_xl : g_xr;
        xlr_body(W, bias, out, bx * 64, ws, xs);
    } else {
        int e = (b - kXlrB) * 256 + threadIdx.x;
        if (e >= kE) return;
        int s = src[e], d = dst[e];
        if (s == d) return;
        int pos = atomicAdd(&g_cur[d], 1);
        int idx = g_off[d] + pos;
        g_csrc[idx] = s;
        float4 a = *(const float4*)&eattr[(size_t)e * 8];
        float4 bb = *(const float4*)&eattr[(size_t)e * 8 + 4];
        *(float4*)&g_eraw[(size_t)idx * 8] = a;
        *(float4*)&g_eraw[(size_t)idx * 8 + 4] = bb;
    }
}

// standalone xlr for layers 1-3
__global__ __launch_bounds__(256) void xlr_gemm(
        const float* __restrict__ Wl, const float* __restrict__ bl,
        const float* __restrict__ Wr, const float* __restrict__ br, int layer) {
    __shared__ __align__(16) float ws[32 * 128];
    __shared__ __align__(16) float xs[32 * 68];
    const float* W = (blockIdx.y == 0 ? Wl : Wr) + layer * kD * kD;
    const float* bias = (blockIdx.y == 0 ? bl : br) + layer * kD;
    float* out = blockIdx.y == 0 ? g_xl : g_xr;
    xlr_body(W, bias, out, blockIdx.x * 64, ws, xs);
}

// ---------------- fused GAT helpers ------------------------------------------
__device__ __forceinline__ void load_s(int S[4], int base, int endm1) {
    int i0 = min(base, endm1), i1 = min(base + 1, endm1);
    int i2 = min(base + 2, endm1), i3 = min(base + 3, endm1);
    S[0] = __ldg(&g_csrc[i0]); S[1] = __ldg(&g_csrc[i1]);
    S[2] = __ldg(&g_csrc[i2]); S[3] = __ldg(&g_csrc[i3]);
}
__device__ __forceinline__ void load_x(float4 X[4], const int S[4], int j0) {
#pragma unroll
    for (int u = 0; u < 4; u++)
        X[u] = __ldg((const float4*)&g_xl[(size_t)S[u] * kD + j0]);
}
__device__ __forceinline__ void pref_eraw(int base, int endm1) {
    int i0 = min(base, endm1), i3 = min(base + 3, endm1);
    asm volatile("prefetch.global.L1 [%0];" :: "l"(&g_eraw[(size_t)i0 * 8]));
    asm volatile("prefetch.global.L1 [%0];" :: "l"(&g_eraw[(size_t)i3 * 8 + 7]));
}

__device__ __forceinline__ void edge_body(
        float4 xls, int eidx, const u64 (&Mr)[8][2], u64 xrb0, u64 xrb1,
        float4 attv, float lself, float& den, u64& acc0, u64& acc1) {
    float4 ra = __ldg((const float4*)&g_eraw[(size_t)eidx * 8]);
    float4 rb = __ldg((const float4*)&g_eraw[(size_t)eidx * 8 + 4]);
    u64 f0 = xrb0, f1 = xrb1;
    float rk[8] = {ra.x, ra.y, ra.z, ra.w, rb.x, rb.y, rb.z, rb.w};
#pragma unroll
    for (int k = 0; k < 8; k++) {
        u64 rp = splat2(rk[k]);
        f0 = fma2(rp, Mr[k][0], f0);
        f1 = fma2(rp, Mr[k][1], f1);
    }
    u64 xp0 = pack2(xls.x, xls.y), xp1 = pack2(xls.z, xls.w);
    f0 = add2(f0, xp0); f1 = add2(f1, xp1);
    float ax, ay, az, aw;
    unpack2(f0, ax, ay); unpack2(f1, az, aw);
    ax = fmaxf(ax, 0.2f * ax); ay = fmaxf(ay, 0.2f * ay);
    az = fmaxf(az, 0.2f * az); aw = fmaxf(aw, 0.2f * aw);
    float l2 = ax * attv.x + ay * attv.y + az * attv.z + aw * attv.w;
    l2 += __shfl_xor_sync(0xffffffffu, l2, 1);
    l2 += __shfl_xor_sync(0xffffffffu, l2, 2);
    float p = __expf(l2 - lself);
    den += p;
    acc0 = fma2(splat2(p), xp0, acc0);
    acc1 = fma2(splat2(p), xp1, acc1);
}

// ---------------- k4..: fused GAT, chunked double-buffered pipeline ---------
__global__ __launch_bounds__(128) void fused_gat(
        const float* __restrict__ att, const float* __restrict__ gbias,
        const float* __restrict__ gam, const float* __restrict__ bet, int layer) {
    int t = threadIdx.x, lane = t & 31;
    int d = (blockIdx.x * 128 + t) >> 5;
    if (d >= kN) return;
    int j0 = lane * 4;

    u64 Mr[8][2];
#pragma unroll
    for (int k = 0; k < 8; k++) {
        float4 mv = *(const float4*)&g_M[layer * 8 * kD + k * kD + j0];
        Mr[k][0] = pack2(mv.x, mv.y);
        Mr[k][1] = pack2(mv.z, mv.w);
    }
    float4 attv = *(const float4*)&att[layer * kD + j0];
    float4 bep4 = *(const float4*)&g_bep[layer * kD + j0];
    float4 xld4 = *(const float4*)&g_xl[d * kD + j0];
    u64 xld0 = pack2(xld4.x, xld4.y), xld1 = pack2(xld4.z, xld4.w);

    int beg = g_off[d], end = g_off[d + 1];

    float a0, a1, a2, a3;
    if (beg == end) {
        a0 = xld4.x; a1 = xld4.y; a2 = xld4.z; a3 = xld4.w;
    } else {
        float4 xr4 = *(const float4*)&g_xr[d * kD + j0];
        u64 xrb0 = pack2(xr4.x + bep4.x, xr4.y + bep4.y);
        u64 xrb1 = pack2(xr4.z + bep4.z, xr4.w + bep4.w);

        // self-loop logit (fixed softmax shift); lraw holds SUM -> divide
        float invc = 1.f / (float)(end - beg);
        float4 lr1 = *(const float4*)&g_lraw[d * 8];
        float4 lr2 = *(const float4*)&g_lraw[d * 8 + 4];
        u64 e0 = add2(xrb0, xld0), e1 = add2(xrb1, xld1);
        {
            float rk[8] = {lr1.x * invc, lr1.y * invc, lr1.z * invc, lr1.w * invc,
                           lr2.x * invc, lr2.y * invc, lr2.z * invc, lr2.w * invc};
#pragma unroll
            for (int k = 0; k < 8; k++) {
                u64 rp = splat2(rk[k]);
                e0 = fma2(rp, Mr[k][0], e0);
                e1 = fma2(rp, Mr[k][1], e1);
            }
        }
        float vx, vy, vz, vw;
        unpack2(e0, vx, vy); unpack2(e1, vz, vw);
        vx = fmaxf(vx, 0.2f * vx); vy = fmaxf(vy, 0.2f * vy);
        vz = fmaxf(vz, 0.2f * vz); vw = fmaxf(vw, 0.2f * vw);
        float lself = vx * attv.x + vy * attv.y + vz * attv.z + vw * attv.w;
        lself += __shfl_xor_sync(0xffffffffu, lself, 1);
        lself += __shfl_xor_sync(0xffffffffu, lself, 2);

        float den = 1.f;
        u64 acc0 = xld0, acc1 = xld1;

        // ---- chunked (4-edge) double-buffered pipeline ----
        int endm1 = end - 1;
        int sA[4], sB[4];
        float4 xA[4], xB[4];
        load_s(sA, beg, endm1);
        load_x(xA, sA, j0);
        load_s(sB, beg + 4, endm1);
        pref_eraw(beg, endm1);
        int cs = beg;
        for (;;) {
            // phase A: process xA chunk; prefetch xl for cs+4 (sB ready),
            // csrc for cs+8, eraw lines for cs+4
            load_x(xB, sB, j0);
            load_s(sA, cs + 8, endm1);
            pref_eraw(cs + 4, endm1);
            int cnt = end - cs;
            edge_body(xA[0], cs, Mr, xrb0, xrb1, attv, lself, den, acc0, acc1);
            if (cnt > 1) edge_body(xA[1], cs + 1, Mr, xrb0, xrb1, attv, lself, den, acc0, acc1);
            if (cnt > 2) edge_body(xA[2], cs + 2, Mr, xrb0, xrb1, attv, lself, den, acc0, acc1);
            if (cnt > 3) edge_body(xA[3], cs + 3, Mr, xrb0, xrb1, attv, lself, den, acc0, acc1);
            cs += 4;
            if (cs >= end) break;
            // phase B: roles swapped
            load_x(xA, sA, j0);
            load_s(sB, cs + 8, endm1);
            pref_eraw(cs + 4, endm1);
            cnt = end - cs;
            edge_body(xB[0], cs, Mr, xrb0, xrb1, attv, lself, den, acc0, acc1);
            if (cnt > 1) edge_body(xB[1], cs + 1, Mr, xrb0, xrb1, attv, lself, den, acc0, acc1);
            if (cnt > 2) edge_body(xB[2], cs + 2, Mr, xrb0, xrb1, attv, lself, den, acc0, acc1);
            if (cnt > 3) edge_body(xB[3], cs + 3, Mr, xrb0, xrb1, attv, lself, den, acc0, acc1);
            cs += 4;
            if (cs >= end) break;
        }
        float inv = 1.f / den;
        float c0, c1, c2, c3;
        unpack2(acc0, c0, c1); unpack2(acc1, c2, c3);
        a0 = c0 * inv; a1 = c1 * inv; a2 = c2 * inv; a3 = c3 * inv;
    }

    float4 gb = *(const float4*)&gbias[layer * kD + j0];
    float4 gm = *(const float4*)&gam[layer * kD + j0];
    float4 bt = *(const float4*)&bet[layer * kD + j0];
    float w0 = gm.x * (a0 + gb.x) * kBNS + bt.x;
    float w1 = gm.y * (a1 + gb.y) * kBNS + bt.y;
    float w2 = gm.z * (a2 + gb.z) * kBNS + bt.z;
    float w3 = gm.w * (a3 + gb.w) * kBNS + bt.w;
    float4 o;
    o.x = w0 > 0.f ? w0 : expm1f(w0);
    o.y = w1 > 0.f ? w1 : expm1f(w1);
    o.z = w2 > 0.f ? w2 : expm1f(w2);
    o.w = w3 > 0.f ? w3 : expm1f(w3);
    *(float4*)&g_x[d * kD + j0] = o;
}

// ---------------- pool + head + cleanup -------------------------------------
__global__ void pool(const int* __restrict__ batch) {
    int g = blockIdx.x;
    int t = threadIdx.x;   // 128
    __shared__ int slo, shi;
    if (t == 0) {
        int lo = 0, hi = kN;
        while (lo < hi) { int mid = (lo + hi) >> 1; if (batch[mid] < g) lo = mid + 1; else hi = mid; }
        slo = lo;
        hi = kN;
        while (lo < hi) { int mid = (lo + hi) >> 1; if (batch[mid] < g + 1) lo = mid + 1; else hi = mid; }
        shi = lo;
    }
    __syncthreads();
    int lo = slo, hi = shi;
    float s = 0.f;
    for (int n = lo; n < hi; n++) s += g_x[n * kD + t];
    g_gsum[g * kD + t] = s / fmaxf((float)(hi - lo), 1.f);
}

__global__ void head(const float* __restrict__ hW, const float* __restrict__ hb,
                     float* __restrict__ out) {
    int g = blockIdx.x;
    int lane = threadIdx.x;
    float acc[kNC] = {};
    for (int k = lane; k < kD; k += 32) {
        float mm = g_gsum[g * kD + k];
#pragma unroll
        for (int c = 0; c < kNC; c++) acc[c] += mm * hW[k * kNC + c];
    }
#pragma unroll
    for (int c = 0; c < kNC; c++) {
        float v = acc[c];
#pragma unroll
        for (int o = 16; o > 0; o >>= 1) v += __shfl_down_sync(0xffffffffu, v, o);
        if (lane == 0) out[g * kNC + c] = v + hb[c];
    }
}

__global__ void cleanup() {
    int i = blockIdx.x * blockDim.x + threadIdx.x;
    int stride = gridDim.x * blockDim.x;
    for (int t = i; t < kN; t += stride) { g_deg[t] = 0; g_cur[t] = 0; }
    for (int t = i; t < kN * 8; t += stride) g_lraw[t] = 0.f;
}

// ---------------- launch -----------------------------------------------------
extern "C" void kernel_launch(void* const* d_in, const int* in_sizes, int n_in,
                              void* d_out, int out_size) {
    const int*   x_nodes = (const int*)d_in[0];
    const int*   esrc    = (const int*)d_in[1];
    const int*   edst    = (const int*)d_in[2];
    const float* eattr   = (const float*)d_in[3];
    const int*   batch   = (const int*)d_in[4];
    const float* nemb    = (const float*)d_in[5];
    const float* edge_W  = (const float*)d_in[6];
    const float* edge_b  = (const float*)d_in[7];
    const float* Wl      = (const float*)d_in[8];
    const float* bl      = (const float*)d_in[9];
    const float* Wr      = (const float*)d_in[10];
    const float* br      = (const float*)d_in[11];
    const float* We      = (const float*)d_in[12];
    const float* att     = (const float*)d_in[13];
    const float* gbias   = (const float*)d_in[14];
    const float* bng     = (const float*)d_in[15];
    const float* bnb     = (const float*)d_in[16];
    const float* headW   = (const float*)d_in[17];
    const float* headb   = (const float*)d_in[18];
    float* out = (float*)d_out;

    // 1: encode + degree/lraw + M/bep   (g_deg/g_cur/g_lraw zero from cleanup/.bss)
    mega_prep<<<kEncB + kCntB + kL, 256>>>(x_nodes, nemb, esrc, edst, eattr,
                                           edge_W, edge_b, We);
    // 2: scan
    scan_single<<<1, 1024>>>();
    // 3: xlr layer 0 + scatter (independent, grid-split)
    xlr_scatter<<<kXlrB + kScatB, 256>>>(Wl, bl, Wr, br, esrc, edst, eattr);
    // 4: fused layer 0  (PROFILED SLOT)
    fused_gat<<<(kN * 32 + 127) / 128, 128>>>(att, gbias, bng, bnb, 0);

    for (int i = 1; i < kL; i++) {
        xlr_gemm<<<dim3((kN + 63) / 64, 2), 256>>>(Wl + (size_t)i * kD * kD, bl + (size_t)i * kD,
                                                   Wr + (size_t)i * kD * kD, br + (size_t)i * kD, 0);
        fused_gat<<<(kN * 32 + 127) / 128, 128>>>(att, gbias, bng, bnb, i);
    }

    pool<<<kG, kD>>>(batch);
    head<<<kG, 32>>>(headW, headb, out);
    cleanup<<<512, 256>>>();
}

// round 9
// speedup vs baseline: 1.2007x; 1.2007x over previous
#include <cuda_runtime.h>
#include <math.h>

constexpr int kN   = 50000;
constexpr int kE   = 800000;
constexpr int kG   = 512;
constexpr int kD   = 128;
constexpr int kEE  = 64;
constexpr int kL   = 4;
constexpr int kNC  = 10;
constexpr int kSB  = (kN + 1023) / 1024;
constexpr float kBNS = 0.9999950000374997f;  // (1+1e-5)^-0.5

// grid split constants
constexpr int kEncB  = (kN * kD + 255) / 256;
constexpr int kCntB  = (kE * 8 + 255) / 256;
constexpr int kXlrB  = ((kN + 63) / 64) * 2;
constexpr int kScatB = (kE + 255) / 256;

typedef unsigned long long u64;

// ---------------- f32x2 packed helpers -------------------------------------
__device__ __forceinline__ u64 pack2(float lo, float hi) {
    u64 r; asm("mov.b64 %0,{%1,%2};" : "=l"(r) : "f"(lo), "f"(hi)); return r;
}
__device__ __forceinline__ u64 splat2(float v) { return pack2(v, v); }
__device__ __forceinline__ void unpack2(u64 p, float& lo, float& hi) {
    asm("mov.b64 {%0,%1},%2;" : "=f"(lo), "=f"(hi) : "l"(p));
}
__device__ __forceinline__ u64 fma2(u64 a, u64 b, u64 c) {
    u64 r; asm("fma.rn.f32x2 %0,%1,%2,%3;" : "=l"(r) : "l"(a), "l"(b), "l"(c)); return r;
}
__device__ __forceinline__ u64 add2(u64 a, u64 b) {
    u64 r; asm("add.rn.f32x2 %0,%1,%2;" : "=l"(r) : "l"(a), "l"(b)); return r;
}

// ---------------- scratch ----------------------------------------------------
// g_deg, g_cur, g_lraw are zero at module load (.bss); cleanup re-zeroes them
// at the end of every kernel_launch so the graph replays deterministically.
__device__ float g_x[kN * kD];
__device__ float g_xl[kN * kD];
__device__ float g_xr[kN * kD];
__device__ float g_lraw[kN * 8];      // SUM of incoming raw attrs
__device__ int   g_deg[kN];
__device__ int   g_cur[kN];
__device__ int   g_off[kN + 1];
__device__ int   g_csrc[kE];
__device__ float g_eraw[(size_t)kE * 8];
__device__ float g_M[kL * 8 * kD];
__device__ float g_bep[kL * kD];
__device__ float g_gsum[kG * kD];

// ---------------- k1: node_encode + degree/lraw atomics + make_M ------------
__global__ void mega_prep(const int* __restrict__ xn, const float* __restrict__ emb,
                          const int* __restrict__ src, const int* __restrict__ dst,
                          const float* __restrict__ eattr,
                          const float* __restrict__ eW, const float* __restrict__ eb,
                          const float* __restrict__ We) {
    int b = blockIdx.x;
    if (b < kEncB) {
        int t = b * 256 + threadIdx.x;
        if (t < kN * kD) {
            int n = t >> 7, j = t & 127;
            g_x[t] = emb[xn[n] * kD + j];
        }
    } else if (b < kEncB + kCntB) {
        int t = (b - kEncB) * 256 + threadIdx.x;
        if (t < kE * 8) {
            int e = t >> 3, j = t & 7;
            int s = src[e], d = dst[e];
            if (s != d) {
                atomicAdd(&g_lraw[d * 8 + j], eattr[t]);
                if (j == 0) atomicAdd(&g_deg[d], 1);
            }
        }
    } else {
        int layer = b - kEncB - kCntB;
        const float* w = We + (size_t)layer * kEE * kD;
        for (int r = threadIdx.x; r < 8 * kD; r += 256) {
            int k = r >> 7, j = r & 127;
            float acc = 0.f;
#pragma unroll 8
            for (int u = 0; u < kEE; u++) acc += eW[k * kEE + u] * w[u * kD + j];
            g_M[layer * 8 * kD + r] = acc;
        }
        if (threadIdx.x < kD) {
            float bb = 0.f;
#pragma unroll 8
            for (int u = 0; u < kEE; u++) bb += eb[u] * w[u * kD + threadIdx.x];
            g_bep[layer * kD + threadIdx.x] = bb;
        }
    }
}

// ---------------- k2: single-block shuffle scan ------------------------------
__global__ void scan_single() {
    __shared__ int wtot[32];
    __shared__ int carrysh;
    int t = threadIdx.x, lane = t & 31, w = t >> 5;
    if (t == 0) carrysh = 0;
    __syncthreads();
    for (int c = 0; c < kSB; c++) {
        int n = c * 1024 + t;
        int v = (n < kN) ? g_deg[n] : 0;
        int inc = v;
#pragma unroll
        for (int o = 1; o < 32; o <<= 1) {
            int x = __shfl_up_sync(0xffffffffu, inc, o);
            if (lane >= o) inc += x;
        }
        if (lane == 31) wtot[w] = inc;
        __syncthreads();
        if (w == 0) {
            int wi = wtot[lane];
#pragma unroll
            for (int o = 1; o < 32; o <<= 1) {
                int y = __shfl_up_sync(0xffffffffu, wi, o);
                if (lane >= o) wi += y;
            }
            wtot[lane] = wi;
        }
        __syncthreads();
        int base = carrysh + (w ? wtot[w - 1] : 0);
        if (n < kN) g_off[n] = base + inc - v;
        __syncthreads();
        if (t == 0) carrysh += wtot[31];
        __syncthreads();
    }
    if (t == 0) g_off[kN] = carrysh;
}

// ---------------- xlr GEMM body ----------------------------------------------
__device__ __forceinline__ void xlr_body(const float* __restrict__ W,
                                         const float* __restrict__ bias,
                                         float* __restrict__ out, int n0,
                                         float* ws, float* xs) {
    int t = threadIdx.x;
    int lane = t & 31;
    int w = t >> 5;
    u64 acc[8][2] = {};
    for (int kt = 0; kt < kD; kt += 32) {
#pragma unroll
        for (int r = t; r < 32 * 128; r += 256)
            ws[r] = W[(kt + (r >> 7)) * kD + (r & 127)];
#pragma unroll
        for (int r = t; r < 64 * 32; r += 256) {
            int n = r >> 5, kk = r & 31;
            int nn = n0 + n;
            xs[kk * 68 + n] = (nn < kN) ? g_x[nn * kD + kt + kk] : 0.f;
        }
        __syncthreads();
#pragma unroll
        for (int kk = 0; kk < 32; kk++) {
            ulonglong2 wv = *(const ulonglong2*)&ws[kk * 128 + lane * 4];
            float4 xv0 = *(const float4*)&xs[kk * 68 + w * 8];
            float4 xv1 = *(const float4*)&xs[kk * 68 + w * 8 + 4];
            float xm[8] = {xv0.x, xv0.y, xv0.z, xv0.w, xv1.x, xv1.y, xv1.z, xv1.w};
#pragma unroll
            for (int m = 0; m < 8; m++) {
                u64 xp = splat2(xm[m]);
                acc[m][0] = fma2(xp, wv.x, acc[m][0]);
                acc[m][1] = fma2(xp, wv.y, acc[m][1]);
            }
        }
        __syncthreads();
    }
    float4 bv = *(const float4*)(bias + lane * 4);
#pragma unroll
    for (int m = 0; m < 8; m++) {
        int n = n0 + w * 8 + m;
        if (n < kN) {
            float a0, a1, a2, a3;
            unpack2(acc[m][0], a0, a1);
            unpack2(acc[m][1], a2, a3);
            float4 o = make_float4(a0 + bv.x, a1 + bv.y, a2 + bv.z, a3 + bv.w);
            *(float4*)&out[n * kD + lane * 4] = o;
        }
    }
}

// ---------------- k3: xlr layer0 + scatter_csr (grid split) -----------------
__global__ __launch_bounds__(256) void xlr_scatter(
        const float* __restrict__ Wl, const float* __restrict__ bl,
        const float* __restrict__ Wr, const float* __restrict__ br,
        const int* __restrict__ src, const int* __restrict__ dst,
        const float* __restrict__ eattr) {
    __shared__ __align__(16) float ws[32 * 128];
    __shared__ __align__(16) float xs[32 * 68];
    int b = blockIdx.x;
    if (b < kXlrB) {
        int half = b / (kXlrB / 2);
        int bx = b % (kXlrB / 2);
        const float* W = (half == 0 ? Wl : Wr);
        const float* bias = (half == 0 ? bl : br);
        float* out = half == 0 ? g_xl : g_xr;
        xlr_body(W, bias, out, bx * 64, ws, xs);
    } else {
        int e = (b - kXlrB) * 256 + threadIdx.x;
        if (e >= kE) return;
        int s = src[e], d = dst[e];
        if (s == d) return;
        int pos = atomicAdd(&g_cur[d], 1);
        int idx = g_off[d] + pos;
        g_csrc[idx] = s;
        float4 a = *(const float4*)&eattr[(size_t)e * 8];
        float4 bb = *(const float4*)&eattr[(size_t)e * 8 + 4];
        *(float4*)&g_eraw[(size_t)idx * 8] = a;
        *(float4*)&g_eraw[(size_t)idx * 8 + 4] = bb;
    }
}

// standalone xlr for layers 1-3
__global__ __launch_bounds__(256) void xlr_gemm(
        const float* __restrict__ Wl, const float* __restrict__ bl,
        const float* __restrict__ Wr, const float* __restrict__ br) {
    __shared__ __align__(16) float ws[32 * 128];
    __shared__ __align__(16) float xs[32 * 68];
    const float* W = (blockIdx.y == 0 ? Wl : Wr);
    const float* bias = (blockIdx.y == 0 ? bl : br);
    float* out = blockIdx.y == 0 ? g_xl : g_xr;
    xlr_body(W, bias, out, blockIdx.x * 64, ws, xs);
}

// ---------------- k4 (PROFILED): fused GAT (R6 body, lean registers) --------
__global__ __launch_bounds__(128) void fused_gat(
        const float* __restrict__ att, const float* __restrict__ gbias,
        const float* __restrict__ gam, const float* __restrict__ bet, int layer) {
    int t = threadIdx.x, lane = t & 31;
    int d = (blockIdx.x * 128 + t) >> 5;
    if (d >= kN) return;
    int j0 = lane * 4;

    u64 Mr[8][2];
#pragma unroll
    for (int k = 0; k < 8; k++) {
        float4 mv = *(const float4*)&g_M[layer * 8 * kD + k * kD + j0];
        Mr[k][0] = pack2(mv.x, mv.y);
        Mr[k][1] = pack2(mv.z, mv.w);
    }
    float4 attv = *(const float4*)&att[layer * kD + j0];
    float4 xld4 = *(const float4*)&g_xl[d * kD + j0];
    u64 xld0 = pack2(xld4.x, xld4.y), xld1 = pack2(xld4.z, xld4.w);

    int beg = g_off[d], end = g_off[d + 1];

    float a0, a1, a2, a3;
    if (beg == end) {
        a0 = xld4.x; a1 = xld4.y; a2 = xld4.z; a3 = xld4.w;
    } else {
        float4 bep4 = *(const float4*)&g_bep[layer * kD + j0];
        float4 xr4 = *(const float4*)&g_xr[d * kD + j0];
        u64 xrb0 = pack2(xr4.x + bep4.x, xr4.y + bep4.y);
        u64 xrb1 = pack2(xr4.z + bep4.z, xr4.w + bep4.w);

        // ---- self-loop logit = fixed softmax shift (lraw holds SUM) ----
        float invc = 1.f / (float)(end - beg);
        float4 lr1 = *(const float4*)&g_lraw[d * 8];
        float4 lr2 = *(const float4*)&g_lraw[d * 8 + 4];
        u64 e0 = add2(xrb0, xld0), e1 = add2(xrb1, xld1);
        {
            float rk[8] = {lr1.x * invc, lr1.y * invc, lr1.z * invc, lr1.w * invc,
                           lr2.x * invc, lr2.y * invc, lr2.z * invc, lr2.w * invc};
#pragma unroll
            for (int k = 0; k < 8; k++) {
                u64 rp = splat2(rk[k]);
                e0 = fma2(rp, Mr[k][0], e0);
                e1 = fma2(rp, Mr[k][1], e1);
            }
        }
        float vx, vy, vz, vw;
        unpack2(e0, vx, vy); unpack2(e1, vz, vw);
        vx = fmaxf(vx, 0.2f * vx); vy = fmaxf(vy, 0.2f * vy);
        vz = fmaxf(vz, 0.2f * vz); vw = fmaxf(vw, 0.2f * vw);
        float lself = vx * attv.x + vy * attv.y + vz * attv.z + vw * attv.w;
        lself += __shfl_xor_sync(0xffffffffu, lself, 1);
        lself += __shfl_xor_sync(0xffffffffu, lself, 2);

        float den = 1.f;
        u64 acc0 = xld0, acc1 = xld1;

        // ---- feed-forward edge loop, depth-2 prefetch ----
        int i = beg;
        int sN = g_csrc[i];
        float4 raN = *(const float4*)&g_eraw[(size_t)i * 8];
        float4 rbN = *(const float4*)&g_eraw[(size_t)i * 8 + 4];
        float4 xlN = *(const float4*)&g_xl[sN * kD + j0];
        int sNN = 0; float4 raNN = {}, rbNN = {};
        if (i + 1 < end) {
            sNN = g_csrc[i + 1];
            raNN = *(const float4*)&g_eraw[(size_t)(i + 1) * 8];
            rbNN = *(const float4*)&g_eraw[(size_t)(i + 1) * 8 + 4];
        }
        for (; i < end; i++) {
            float4 xls = xlN, ra = raN, rb = rbN;
            if (i + 1 < end) {
                xlN = *(const float4*)&g_xl[sNN * kD + j0];
                raN = raNN; rbN = rbNN;
            }
            if (i + 2 < end) {
                sNN = g_csrc[i + 2];
                raNN = *(const float4*)&g_eraw[(size_t)(i + 2) * 8];
                rbNN = *(const float4*)&g_eraw[(size_t)(i + 2) * 8 + 4];
            }
            u64 xlsp0 = pack2(xls.x, xls.y), xlsp1 = pack2(xls.z, xls.w);
            u64 f0 = xrb0, f1 = xrb1;
            float rk[8] = {ra.x, ra.y, ra.z, ra.w, rb.x, rb.y, rb.z, rb.w};
#pragma unroll
            for (int k = 0; k < 8; k++) {
                u64 rp = splat2(rk[k]);
                f0 = fma2(rp, Mr[k][0], f0);
                f1 = fma2(rp, Mr[k][1], f1);
            }
            f0 = add2(f0, xlsp0); f1 = add2(f1, xlsp1);
            float ax, ay, az, aw;
            unpack2(f0, ax, ay); unpack2(f1, az, aw);
            ax = fmaxf(ax, 0.2f * ax); ay = fmaxf(ay, 0.2f * ay);
            az = fmaxf(az, 0.2f * az); aw = fmaxf(aw, 0.2f * aw);
            float l2 = ax * attv.x + ay * attv.y + az * attv.z + aw * attv.w;
            l2 += __shfl_xor_sync(0xffffffffu, l2, 1);
            l2 += __shfl_xor_sync(0xffffffffu, l2, 2);

            float p = __expf(l2 - lself);
            den += p;
            u64 pp = splat2(p);
            acc0 = fma2(pp, xlsp0, acc0);
            acc1 = fma2(pp, xlsp1, acc1);
        }
        float inv = 1.f / den;
        float c0, c1, c2, c3;
        unpack2(acc0, c0, c1); unpack2(acc1, c2, c3);
        a0 = c0 * inv; a1 = c1 * inv; a2 = c2 * inv; a3 = c3 * inv;
    }

    // epilogue constants loaded late (short live ranges)
    float4 gb = __ldg((const float4*)&gbias[layer * kD + j0]);
    float4 gm = __ldg((const float4*)&gam[layer * kD + j0]);
    float4 bt = __ldg((const float4*)&bet[layer * kD + j0]);
    float w0 = gm.x * (a0 + gb.x) * kBNS + bt.x;
    float w1 = gm.y * (a1 + gb.y) * kBNS + bt.y;
    float w2 = gm.z * (a2 + gb.z) * kBNS + bt.z;
    float w3 = gm.w * (a3 + gb.w) * kBNS + bt.w;
    float4 o;
    o.x = w0 > 0.f ? w0 : expm1f(w0);
    o.y = w1 > 0.f ? w1 : expm1f(w1);
    o.z = w2 > 0.f ? w2 : expm1f(w2);
    o.w = w3 > 0.f ? w3 : expm1f(w3);
    *(float4*)&g_x[d * kD + j0] = o;
}

// ---------------- pool + head + cleanup -------------------------------------
__global__ void pool(const int* __restrict__ batch) {
    int g = blockIdx.x;
    int t = threadIdx.x;   // 128
    __shared__ int slo, shi;
    if (t == 0) {
        int lo = 0, hi = kN;
        while (lo < hi) { int mid = (lo + hi) >> 1; if (batch[mid] < g) lo = mid + 1; else hi = mid; }
        slo = lo;
        hi = kN;
        while (lo < hi) { int mid = (lo + hi) >> 1; if (batch[mid] < g + 1) lo = mid + 1; else hi = mid; }
        shi = lo;
    }
    __syncthreads();
    int lo = slo, hi = shi;
    float s = 0.f;
    for (int n = lo; n < hi; n++) s += g_x[n * kD + t];
    g_gsum[g * kD + t] = s / fmaxf((float)(hi - lo), 1.f);
}

__global__ void head(const float* __restrict__ hW, const float* __restrict__ hb,
                     float* __restrict__ out) {
    int g = blockIdx.x;
    int lane = threadIdx.x;
    float acc[kNC] = {};
    for (int k = lane; k < kD; k += 32) {
        float mm = g_gsum[g * kD + k];
#pragma unroll
        for (int c = 0; c < kNC; c++) acc[c] += mm * hW[k * kNC + c];
    }
#pragma unroll
    for (int c = 0; c < kNC; c++) {
        float v = acc[c];
#pragma unroll
        for (int o = 16; o > 0; o >>= 1) v += __shfl_down_sync(0xffffffffu, v, o);
        if (lane == 0) out[g * kNC + c] = v + hb[c];
    }
}

__global__ void cleanup() {
    int i = blockIdx.x * blockDim.x + threadIdx.x;
    int stride = gridDim.x * blockDim.x;
    for (int t = i; t < kN; t += stride) { g_deg[t] = 0; g_cur[t] = 0; }
    for (int t = i; t < kN * 8; t += stride) g_lraw[t] = 0.f;
}

// ---------------- launch -----------------------------------------------------
extern "C" void kernel_launch(void* const* d_in, const int* in_sizes, int n_in,
                              void* d_out, int out_size) {
    const int*   x_nodes = (const int*)d_in[0];
    const int*   esrc    = (const int*)d_in[1];
    const int*   edst    = (const int*)d_in[2];
    const float* eattr   = (const float*)d_in[3];
    const int*   batch   = (const int*)d_in[4];
    const float* nemb    = (const float*)d_in[5];
    const float* edge_W  = (const float*)d_in[6];
    const float* edge_b  = (const float*)d_in[7];
    const float* Wl      = (const float*)d_in[8];
    const float* bl      = (const float*)d_in[9];
    const float* Wr      = (const float*)d_in[10];
    const float* br      = (const float*)d_in[11];
    const float* We      = (const float*)d_in[12];
    const float* att     = (const float*)d_in[13];
    const float* gbias   = (const float*)d_in[14];
    const float* bng     = (const float*)d_in[15];
    const float* bnb     = (const float*)d_in[16];
    const float* headW   = (const float*)d_in[17];
    const float* headb   = (const float*)d_in[18];
    float* out = (float*)d_out;

    mega_prep<<<kEncB + kCntB + kL, 256>>>(x_nodes, nemb, esrc, edst, eattr,
                                           edge_W, edge_b, We);          // 1
    scan_single<<<1, 1024>>>();                                          // 2
    xlr_scatter<<<kXlrB + kScatB, 256>>>(Wl, bl, Wr, br, esrc, edst, eattr); // 3
    fused_gat<<<(kN * 32 + 127) / 128, 128>>>(att, gbias, bng, bnb, 0);  // 4 (profiled)

    for (int i = 1; i < kL; i++) {
        xlr_gemm<<<dim3((kN + 63) / 64, 2), 256>>>(
            Wl + (size_t)i * kD * kD, bl + (size_t)i * kD,
            Wr + (size_t)i * kD * kD, br + (size_t)i * kD);
        fused_gat<<<(kN * 32 + 127) / 128, 128>>>(att, gbias, bng, bnb, i);
    }

    pool<<<kG, kD>>>(batch);
    head<<<kG, 32>>>(headW, headb, out);
    cleanup<<<512, 256>>>();
}

// round 10
// speedup vs baseline: 1.2053x; 1.0039x over previous
#include <cuda_runtime.h>
#include <math.h>

constexpr int kN   = 50000;
constexpr int kE   = 800000;
constexpr int kG   = 512;
constexpr int kD   = 128;
constexpr int kEE  = 64;
constexpr int kL   = 4;
constexpr int kNC  = 10;
constexpr int kSB  = (kN + 1023) / 1024;
constexpr float kBNS = 0.9999950000374997f;  // (1+1e-5)^-0.5

// grid split constants
constexpr int kEncB  = (kN * kD + 255) / 256;
constexpr int kCntB  = (kE * 8 + 255) / 256;
constexpr int kXlrB  = ((kN + 63) / 64) * 2;
constexpr int kScatB = (kE + 255) / 256;

typedef unsigned long long u64;

// ---------------- f32x2 packed helpers -------------------------------------
__device__ __forceinline__ u64 pack2(float lo, float hi) {
    u64 r; asm("mov.b64 %0,{%1,%2};" : "=l"(r) : "f"(lo), "f"(hi)); return r;
}
__device__ __forceinline__ u64 splat2(float v) { return pack2(v, v); }
__device__ __forceinline__ void unpack2(u64 p, float& lo, float& hi) {
    asm("mov.b64 {%0,%1},%2;" : "=f"(lo), "=f"(hi) : "l"(p));
}
__device__ __forceinline__ u64 fma2(u64 a, u64 b, u64 c) {
    u64 r; asm("fma.rn.f32x2 %0,%1,%2,%3;" : "=l"(r) : "l"(a), "l"(b), "l"(c)); return r;
}
__device__ __forceinline__ u64 add2(u64 a, u64 b) {
    u64 r; asm("add.rn.f32x2 %0,%1,%2;" : "=l"(r) : "l"(a), "l"(b)); return r;
}

// ---------------- scratch ----------------------------------------------------
__device__ float g_x[kN * kD];
__device__ float g_xl[kN * kD];
__device__ float g_xr[kN * kD];
__device__ float g_lraw[kN * 8];      // SUM of incoming raw attrs
__device__ int   g_deg[kN];
__device__ int   g_cur[kN];
__device__ int   g_off[kN + 1];
__device__ int   g_csrc[kE];
__device__ float g_eraw[(size_t)kE * 8];
__device__ float g_M[kL * 8 * kD];
__device__ float g_bep[kL * kD];
__device__ float g_gsum[kG * kD];

// ---------------- k1: node_encode + degree/lraw atomics + make_M ------------
__global__ void mega_prep(const int* __restrict__ xn, const float* __restrict__ emb,
                          const int* __restrict__ src, const int* __restrict__ dst,
                          const float* __restrict__ eattr,
                          const float* __restrict__ eW, const float* __restrict__ eb,
                          const float* __restrict__ We) {
    int b = blockIdx.x;
    if (b < kEncB) {
        int t = b * 256 + threadIdx.x;
        if (t < kN * kD) {
            int n = t >> 7, j = t & 127;
            g_x[t] = emb[xn[n] * kD + j];
        }
    } else if (b < kEncB + kCntB) {
        int t = (b - kEncB) * 256 + threadIdx.x;
        if (t < kE * 8) {
            int e = t >> 3, j = t & 7;
            int s = src[e], d = dst[e];
            if (s != d) {
                atomicAdd(&g_lraw[d * 8 + j], eattr[t]);
                if (j == 0) atomicAdd(&g_deg[d], 1);
            }
        }
    } else {
        int layer = b - kEncB - kCntB;
        const float* w = We + (size_t)layer * kEE * kD;
        for (int r = threadIdx.x; r < 8 * kD; r += 256) {
            int k = r >> 7, j = r & 127;
            float acc = 0.f;
#pragma unroll 8
            for (int u = 0; u < kEE; u++) acc += eW[k * kEE + u] * w[u * kD + j];
            g_M[layer * 8 * kD + r] = acc;
        }
        if (threadIdx.x < kD) {
            float bb = 0.f;
#pragma unroll 8
            for (int u = 0; u < kEE; u++) bb += eb[u] * w[u * kD + threadIdx.x];
            g_bep[layer * kD + threadIdx.x] = bb;
        }
    }
}

// ---------------- k2: single-block shuffle scan ------------------------------
__global__ void scan_single() {
    __shared__ int wtot[32];
    __shared__ int carrysh;
    int t = threadIdx.x, lane = t & 31, w = t >> 5;
    if (t == 0) carrysh = 0;
    __syncthreads();
    for (int c = 0; c < kSB; c++) {
        int n = c * 1024 + t;
        int v = (n < kN) ? g_deg[n] : 0;
        int inc = v;
#pragma unroll
        for (int o = 1; o < 32; o <<= 1) {
            int x = __shfl_up_sync(0xffffffffu, inc, o);
            if (lane >= o) inc += x;
        }
        if (lane == 31) wtot[w] = inc;
        __syncthreads();
        if (w == 0) {
            int wi = wtot[lane];
#pragma unroll
            for (int o = 1; o < 32; o <<= 1) {
                int y = __shfl_up_sync(0xffffffffu, wi, o);
                if (lane >= o) wi += y;
            }
            wtot[lane] = wi;
        }
        __syncthreads();
        int base = carrysh + (w ? wtot[w - 1] : 0);
        if (n < kN) g_off[n] = base + inc - v;
        __syncthreads();
        if (t == 0) carrysh += wtot[31];
        __syncthreads();
    }
    if (t == 0) g_off[kN] = carrysh;
}

// ---------------- xlr GEMM body ----------------------------------------------
__device__ __forceinline__ void xlr_body(const float* __restrict__ W,
                                         const float* __restrict__ bias,
                                         float* __restrict__ out, int n0,
                                         float* ws, float* xs) {
    int t = threadIdx.x;
    int lane = t & 31;
    int w = t >> 5;
    u64 acc[8][2] = {};
    for (int kt = 0; kt < kD; kt += 32) {
#pragma unroll
        for (int r = t; r < 32 * 128; r += 256)
            ws[r] = W[(kt + (r >> 7)) * kD + (r & 127)];
#pragma unroll
        for (int r = t; r < 64 * 32; r += 256) {
            int n = r >> 5, kk = r & 31;
            int nn = n0 + n;
            xs[kk * 68 + n] = (nn < kN) ? g_x[nn * kD + kt + kk] : 0.f;
        }
        __syncthreads();
#pragma unroll
        for (int kk = 0; kk < 32; kk++) {
            ulonglong2 wv = *(const ulonglong2*)&ws[kk * 128 + lane * 4];
            float4 xv0 = *(const float4*)&xs[kk * 68 + w * 8];
            float4 xv1 = *(const float4*)&xs[kk * 68 + w * 8 + 4];
            float xm[8] = {xv0.x, xv0.y, xv0.z, xv0.w, xv1.x, xv1.y, xv1.z, xv1.w};
#pragma unroll
            for (int m = 0; m < 8; m++) {
                u64 xp = splat2(xm[m]);
                acc[m][0] = fma2(xp, wv.x, acc[m][0]);
                acc[m][1] = fma2(xp, wv.y, acc[m][1]);
            }
        }
        __syncthreads();
    }
    float4 bv = *(const float4*)(bias + lane * 4);
#pragma unroll
    for (int m = 0; m < 8; m++) {
        int n = n0 + w * 8 + m;
        if (n < kN) {
            float a0, a1, a2, a3;
            unpack2(acc[m][0], a0, a1);
            unpack2(acc[m][1], a2, a3);
            float4 o = make_float4(a0 + bv.x, a1 + bv.y, a2 + bv.z, a3 + bv.w);
            *(float4*)&out[n * kD + lane * 4] = o;
        }
    }
}

// ---------------- k3: xlr layer0 + scatter_csr (grid split) -----------------
__global__ __launch_bounds__(256) void xlr_scatter(
        const float* __restrict__ Wl, const float* __restrict__ bl,
        const float* __restrict__ Wr, const float* __restrict__ br,
        const int* __restrict__ src, const int* __restrict__ dst,
        const float* __restrict__ eattr) {
    __shared__ __align__(16) float ws[32 * 128];
    __shared__ __align__(16) float xs[32 * 68];
    int b = blockIdx.x;
    if (b < kXlrB) {
        int half = b / (kXlrB / 2);
        int bx = b % (kXlrB / 2);
        const float* W = (half == 0 ? Wl : Wr);
        const float* bias = (half == 0 ? bl : br);
        float* out = half == 0 ? g_xl : g_xr;
        xlr_body(W, bias, out, bx * 64, ws, xs);
    } else {
        int e = (b - kXlrB) * 256 + threadIdx.x;
        if (e >= kE) return;
        int s = src[e], d = dst[e];
        if (s == d) return;
        int pos = atomicAdd(&g_cur[d], 1);
        int idx = g_off[d] + pos;
        g_csrc[idx] = s;
        float4 a = *(const float4*)&eattr[(size_t)e * 8];
        float4 bb = *(const float4*)&eattr[(size_t)e * 8 + 4];
        *(float4*)&g_eraw[(size_t)idx * 8] = a;
        *(float4*)&g_eraw[(size_t)idx * 8 + 4] = bb;
    }
}

// standalone xlr for layers 1-3
__global__ __launch_bounds__(256) void xlr_gemm(
        const float* __restrict__ Wl, const float* __restrict__ bl,
        const float* __restrict__ Wr, const float* __restrict__ br) {
    __shared__ __align__(16) float ws[32 * 128];
    __shared__ __align__(16) float xs[32 * 68];
    const float* W = (blockIdx.y == 0 ? Wl : Wr);
    const float* bias = (blockIdx.y == 0 ? bl : br);
    float* out = blockIdx.y == 0 ? g_xl : g_xr;
    xlr_body(W, bias, out, blockIdx.x * 64, ws, xs);
}

// ---------------- per-edge math ----------------------------------------------
__device__ __forceinline__ void egat_edge(
        float4 xls, float4 ra, float4 rb,
        const u64 (&Mr)[8][2], u64 xrb0, u64 xrb1, float4 attv, float lself,
        float& den, u64& acc0, u64& acc1) {
    u64 f0 = xrb0, f1 = xrb1;
    float rk[8] = {ra.x, ra.y, ra.z, ra.w, rb.x, rb.y, rb.z, rb.w};
#pragma unroll
    for (int k = 0; k < 8; k++) {
        u64 rp = splat2(rk[k]);
        f0 = fma2(rp, Mr[k][0], f0);
        f1 = fma2(rp, Mr[k][1], f1);
    }
    u64 xp0 = pack2(xls.x, xls.y), xp1 = pack2(xls.z, xls.w);
    f0 = add2(f0, xp0); f1 = add2(f1, xp1);
    float ax, ay, az, aw;
    unpack2(f0, ax, ay); unpack2(f1, az, aw);
    ax = fmaxf(ax, 0.2f * ax); ay = fmaxf(ay, 0.2f * ay);
    az = fmaxf(az, 0.2f * az); aw = fmaxf(aw, 0.2f * aw);
    float l2 = ax * attv.x + ay * attv.y + az * attv.z + aw * attv.w;
    l2 += __shfl_xor_sync(0xffffffffu, l2, 1);
    l2 += __shfl_xor_sync(0xffffffffu, l2, 2);
    float p = __expf(l2 - lself);
    den += p;
    u64 pp = splat2(p);
    acc0 = fma2(pp, xp0, acc0);
    acc1 = fma2(pp, xp1, acc1);
}

// ---------------- k4 (PROFILED): fused GAT, pair ping-pong (no rotation) ----
__global__ __launch_bounds__(128) void fused_gat(
        const float* __restrict__ att, const float* __restrict__ gbias,
        const float* __restrict__ gam, const float* __restrict__ bet, int layer) {
    int t = threadIdx.x, lane = t & 31;
    int d = (blockIdx.x * 128 + t) >> 5;
    if (d >= kN) return;
    int j0 = lane * 4;

    u64 Mr[8][2];
#pragma unroll
    for (int k = 0; k < 8; k++) {
        float4 mv = *(const float4*)&g_M[layer * 8 * kD + k * kD + j0];
        Mr[k][0] = pack2(mv.x, mv.y);
        Mr[k][1] = pack2(mv.z, mv.w);
    }
    float4 attv = *(const float4*)&att[layer * kD + j0];
    float4 xld4 = *(const float4*)&g_xl[d * kD + j0];
    u64 xld0 = pack2(xld4.x, xld4.y), xld1 = pack2(xld4.z, xld4.w);

    int beg = g_off[d], end = g_off[d + 1];
    int cnt = end - beg;

    float a0, a1, a2, a3;
    if (cnt == 0) {
        a0 = xld4.x; a1 = xld4.y; a2 = xld4.z; a3 = xld4.w;
    } else {
        float4 bep4 = *(const float4*)&g_bep[layer * kD + j0];
        float4 xr4 = *(const float4*)&g_xr[d * kD + j0];
        u64 xrb0 = pack2(xr4.x + bep4.x, xr4.y + bep4.y);
        u64 xrb1 = pack2(xr4.z + bep4.z, xr4.w + bep4.w);

        // ---- self-loop logit = fixed softmax shift (lraw holds SUM) ----
        float invc = 1.f / (float)cnt;
        float4 lr1 = *(const float4*)&g_lraw[d * 8];
        float4 lr2 = *(const float4*)&g_lraw[d * 8 + 4];
        u64 e0 = add2(xrb0, xld0), e1 = add2(xrb1, xld1);
        {
            float rk[8] = {lr1.x * invc, lr1.y * invc, lr1.z * invc, lr1.w * invc,
                           lr2.x * invc, lr2.y * invc, lr2.z * invc, lr2.w * invc};
#pragma unroll
            for (int k = 0; k < 8; k++) {
                u64 rp = splat2(rk[k]);
                e0 = fma2(rp, Mr[k][0], e0);
                e1 = fma2(rp, Mr[k][1], e1);
            }
        }
        float vx, vy, vz, vw;
        unpack2(e0, vx, vy); unpack2(e1, vz, vw);
        vx = fmaxf(vx, 0.2f * vx); vy = fmaxf(vy, 0.2f * vy);
        vz = fmaxf(vz, 0.2f * vz); vw = fmaxf(vw, 0.2f * vw);
        float lself = vx * attv.x + vy * attv.y + vz * attv.z + vw * attv.w;
        lself += __shfl_xor_sync(0xffffffffu, lself, 1);
        lself += __shfl_xor_sync(0xffffffffu, lself, 2);

        float den = 1.f;
        u64 acc0 = xld0, acc1 = xld1;

        int i = beg;
        if (cnt >= 4) {
            // preload pair A (sd + xl) and sd of pair B
            int sA0 = g_csrc[i], sA1 = g_csrc[i + 1];
            float4 xA0 = *(const float4*)&g_xl[(size_t)sA0 * kD + j0];
            float4 xA1 = *(const float4*)&g_xl[(size_t)sA1 * kD + j0];
            int sB0 = g_csrc[i + 2], sB1 = g_csrc[i + 3];
            float4 xB0, xB1;
            for (;;) {
                // ---- phase A: prefetch B's xl + next sd; process pair at i ----
                xB0 = *(const float4*)&g_xl[(size_t)sB0 * kD + j0];
                xB1 = *(const float4*)&g_xl[(size_t)sB1 * kD + j0];
                if (i + 5 < end) { sA0 = g_csrc[i + 4]; sA1 = g_csrc[i + 5]; }
                egat_edge(xA0, *(const float4*)&g_eraw[(size_t)i * 8],
                          *(const float4*)&g_eraw[(size_t)i * 8 + 4],
                          Mr, xrb0, xrb1, attv, lself, den, acc0, acc1);
                egat_edge(xA1, *(const float4*)&g_eraw[(size_t)(i + 1) * 8],
                          *(const float4*)&g_eraw[(size_t)(i + 1) * 8 + 4],
                          Mr, xrb0, xrb1, attv, lself, den, acc0, acc1);
                i += 2;
                if (i + 3 >= end) {
                    egat_edge(xB0, *(const float4*)&g_eraw[(size_t)i * 8],
                              *(const float4*)&g_eraw[(size_t)i * 8 + 4],
                              Mr, xrb0, xrb1, attv, lself, den, acc0, acc1);
                    egat_edge(xB1, *(const float4*)&g_eraw[(size_t)(i + 1) * 8],
                              *(const float4*)&g_eraw[(size_t)(i + 1) * 8 + 4],
                              Mr, xrb0, xrb1, attv, lself, den, acc0, acc1);
                    i += 2;
                    break;
                }
                // ---- phase B (roles swapped) ----
                xA0 = *(const float4*)&g_xl[(size_t)sA0 * kD + j0];
                xA1 = *(const float4*)&g_xl[(size_t)sA1 * kD + j0];
                if (i + 5 < end) { sB0 = g_csrc[i + 4]; sB1 = g_csrc[i + 5]; }
                egat_edge(xB0, *(const float4*)&g_eraw[(size_t)i * 8],
                          *(const float4*)&g_eraw[(size_t)i * 8 + 4],
                          Mr, xrb0, xrb1, attv, lself, den, acc0, acc1);
                egat_edge(xB1, *(const float4*)&g_eraw[(size_t)(i + 1) * 8],
                          *(const float4*)&g_eraw[(size_t)(i + 1) * 8 + 4],
                          Mr, xrb0, xrb1, attv, lself, den, acc0, acc1);
                i += 2;
                if (i + 3 >= end) {
                    egat_edge(xA0, *(const float4*)&g_eraw[(size_t)i * 8],
                              *(const float4*)&g_eraw[(size_t)i * 8 + 4],
                              Mr, xrb0, xrb1, attv, lself, den, acc0, acc1);
                    egat_edge(xA1, *(const float4*)&g_eraw[(size_t)(i + 1) * 8],
                              *(const float4*)&g_eraw[(size_t)(i + 1) * 8 + 4],
                              Mr, xrb0, xrb1, attv, lself, den, acc0, acc1);
                    i += 2;
                    break;
                }
            }
        }
        // scalar tail (<=3 edges, or all edges when cnt < 4)
        for (; i < end; i++) {
            int s = g_csrc[i];
            float4 xls = *(const float4*)&g_xl[(size_t)s * kD + j0];
            egat_edge(xls, *(const float4*)&g_eraw[(size_t)i * 8],
                      *(const float4*)&g_eraw[(size_t)i * 8 + 4],
                      Mr, xrb0, xrb1, attv, lself, den, acc0, acc1);
        }
        float inv = 1.f / den;
        float c0, c1, c2, c3;
        unpack2(acc0, c0, c1); unpack2(acc1, c2, c3);
        a0 = c0 * inv; a1 = c1 * inv; a2 = c2 * inv; a3 = c3 * inv;
    }

    float4 gb = __ldg((const float4*)&gbias[layer * kD + j0]);
    float4 gm = __ldg((const float4*)&gam[layer * kD + j0]);
    float4 bt = __ldg((const float4*)&bet[layer * kD + j0]);
    float w0 = gm.x * (a0 + gb.x) * kBNS + bt.x;
    float w1 = gm.y * (a1 + gb.y) * kBNS + bt.y;
    float w2 = gm.z * (a2 + gb.z) * kBNS + bt.z;
    float w3 = gm.w * (a3 + gb.w) * kBNS + bt.w;
    float4 o;
    o.x = w0 > 0.f ? w0 : expm1f(w0);
    o.y = w1 > 0.f ? w1 : expm1f(w1);
    o.z = w2 > 0.f ? w2 : expm1f(w2);
    o.w = w3 > 0.f ? w3 : expm1f(w3);
    *(float4*)&g_x[d * kD + j0] = o;
}

// ---------------- pool + head + cleanup -------------------------------------
__global__ void pool(const int* __restrict__ batch) {
    int g = blockIdx.x;
    int t = threadIdx.x;   // 128
    __shared__ int slo, shi;
    if (t == 0) {
        int lo = 0, hi = kN;
        while (lo < hi) { int mid = (lo + hi) >> 1; if (batch[mid] < g) lo = mid + 1; else hi = mid; }
        slo = lo;
        hi = kN;
        while (lo < hi) { int mid = (lo + hi) >> 1; if (batch[mid] < g + 1) lo = mid + 1; else hi = mid; }
        shi = lo;
    }
    __syncthreads();
    int lo = slo, hi = shi;
    float s = 0.f;
    for (int n = lo; n < hi; n++) s += g_x[n * kD + t];
    g_gsum[g * kD + t] = s / fmaxf((float)(hi - lo), 1.f);
}

__global__ void head(const float* __restrict__ hW, const float* __restrict__ hb,
                     float* __restrict__ out) {
    int g = blockIdx.x;
    int lane = threadIdx.x;
    float acc[kNC] = {};
    for (int k = lane; k < kD; k += 32) {
        float mm = g_gsum[g * kD + k];
#pragma unroll
        for (int c = 0; c < kNC; c++) acc[c] += mm * hW[k * kNC + c];
    }
#pragma unroll
    for (int c = 0; c < kNC; c++) {
        float v = acc[c];
#pragma unroll
        for (int o = 16; o > 0; o >>= 1) v += __shfl_down_sync(0xffffffffu, v, o);
        if (lane == 0) out[g * kNC + c] = v + hb[c];
    }
}

__global__ void cleanup() {
    int i = blockIdx.x * blockDim.x + threadIdx.x;
    int stride = gridDim.x * blockDim.x;
    for (int t = i; t < kN; t += stride) { g_deg[t] = 0; g_cur[t] = 0; }
    for (int t = i; t < kN * 8; t += stride) g_lraw[t] = 0.f;
}

// ---------------- launch -----------------------------------------------------
extern "C" void kernel_launch(void* const* d_in, const int* in_sizes, int n_in,
                              void* d_out, int out_size) {
    const int*   x_nodes = (const int*)d_in[0];
    const int*   esrc    = (const int*)d_in[1];
    const int*   edst    = (const int*)d_in[2];
    const float* eattr   = (const float*)d_in[3];
    const int*   batch   = (const int*)d_in[4];
    const float* nemb    = (const float*)d_in[5];
    const float* edge_W  = (const float*)d_in[6];
    const float* edge_b  = (const float*)d_in[7];
    const float* Wl      = (const float*)d_in[8];
    const float* bl      = (const float*)d_in[9];
    const float* Wr      = (const float*)d_in[10];
    const float* br      = (const float*)d_in[11];
    const float* We      = (const float*)d_in[12];
    const float* att     = (const float*)d_in[13];
    const float* gbias   = (const float*)d_in[14];
    const float* bng     = (const float*)d_in[15];
    const float* bnb     = (const float*)d_in[16];
    const float* headW   = (const float*)d_in[17];
    const float* headb   = (const float*)d_in[18];
    float* out = (float*)d_out;

    mega_prep<<<kEncB + kCntB + kL, 256>>>(x_nodes, nemb, esrc, edst, eattr,
                                           edge_W, edge_b, We);              // 1
    scan_single<<<1, 1024>>>();                                              // 2
    xlr_scatter<<<kXlrB + kScatB, 256>>>(Wl, bl, Wr, br, esrc, edst, eattr); // 3
    fused_gat<<<(kN * 32 + 127) / 128, 128>>>(att, gbias, bng, bnb, 0);      // 4 (profiled)

    for (int i = 1; i < kL; i++) {
        xlr_gemm<<<dim3((kN + 63) / 64, 2), 256>>>(
            Wl + (size_t)i * kD * kD, bl + (size_t)i * kD,
            Wr + (size_t)i * kD * kD, br + (size_t)i * kD);
        fused_gat<<<(kN * 32 + 127) / 128, 128>>>(att, gbias, bng, bnb, i);
    }

    pool<<<kG, kD>>>(batch);
    head<<<kG, 32>>>(headW, headb, out);
    cleanup<<<512, 256>>>();
}

// round 11
// speedup vs baseline: 1.3387x; 1.1106x over previous
#include <cuda_runtime.h>
#include <math.h>

constexpr int kN   = 50000;
constexpr int kE   = 800000;
constexpr int kG   = 512;
constexpr int kD   = 128;
constexpr int kEE  = 64;
constexpr int kL   = 4;
constexpr int kNC  = 10;
constexpr int kSB  = (kN + 1023) / 1024;
constexpr float kBNS = 0.9999950000374997f;  // (1+1e-5)^-0.5

// grid split constants
constexpr int kEncB  = (kN * kD + 255) / 256;
constexpr int kCntB  = (kE * 8 + 255) / 256;
constexpr int kXlrB  = ((kN + 63) / 64) * 2;
constexpr int kScatB = (kE + 255) / 256;
constexpr int kGatB  = 740;          // 148 SMs x 5 resident blocks (96 regs, 128 thr)
constexpr int kChunk = 4;            // nodes per work-steal grab

typedef unsigned long long u64;

// ---------------- f32x2 packed helpers -------------------------------------
__device__ __forceinline__ u64 pack2(float lo, float hi) {
    u64 r; asm("mov.b64 %0,{%1,%2};" : "=l"(r) : "f"(lo), "f"(hi)); return r;
}
__device__ __forceinline__ u64 splat2(float v) { return pack2(v, v); }
__device__ __forceinline__ void unpack2(u64 p, float& lo, float& hi) {
    asm("mov.b64 {%0,%1},%2;" : "=f"(lo), "=f"(hi) : "l"(p));
}
__device__ __forceinline__ u64 fma2(u64 a, u64 b, u64 c) {
    u64 r; asm("fma.rn.f32x2 %0,%1,%2,%3;" : "=l"(r) : "l"(a), "l"(b), "l"(c)); return r;
}
__device__ __forceinline__ u64 add2(u64 a, u64 b) {
    u64 r; asm("add.rn.f32x2 %0,%1,%2;" : "=l"(r) : "l"(a), "l"(b)); return r;
}

// ---------------- scratch ----------------------------------------------------
__device__ float g_x[kN * kD];
__device__ float g_xl[kN * kD];
__device__ float g_xr[kN * kD];
__device__ float g_lraw[kN * 8];      // SUM of incoming raw attrs
__device__ int   g_deg[kN];
__device__ int   g_cur[kN];
__device__ int   g_off[kN + 1];
__device__ int   g_csrc[kE];
__device__ float g_eraw[(size_t)kE * 8];
__device__ float g_M[kL * 8 * kD];
__device__ float g_bep[kL * kD];
__device__ float g_gsum[kG * kD];
__device__ int   g_work[kL];          // per-layer work-steal counters (.bss zero)

// ---------------- k1: node_encode + degree/lraw atomics + make_M ------------
__global__ void mega_prep(const int* __restrict__ xn, const float* __restrict__ emb,
                          const int* __restrict__ src, const int* __restrict__ dst,
                          const float* __restrict__ eattr,
                          const float* __restrict__ eW, const float* __restrict__ eb,
                          const float* __restrict__ We) {
    int b = blockIdx.x;
    if (b < kEncB) {
        int t = b * 256 + threadIdx.x;
        if (t < kN * kD) {
            int n = t >> 7, j = t & 127;
            g_x[t] = emb[xn[n] * kD + j];
        }
    } else if (b < kEncB + kCntB) {
        int t = (b - kEncB) * 256 + threadIdx.x;
        if (t < kE * 8) {
            int e = t >> 3, j = t & 7;
            int s = src[e], d = dst[e];
            if (s != d) {
                atomicAdd(&g_lraw[d * 8 + j], eattr[t]);
                if (j == 0) atomicAdd(&g_deg[d], 1);
            }
        }
    } else {
        int layer = b - kEncB - kCntB;
        const float* w = We + (size_t)layer * kEE * kD;
        for (int r = threadIdx.x; r < 8 * kD; r += 256) {
            int k = r >> 7, j = r & 127;
            float acc = 0.f;
#pragma unroll 8
            for (int u = 0; u < kEE; u++) acc += eW[k * kEE + u] * w[u * kD + j];
            g_M[layer * 8 * kD + r] = acc;
        }
        if (threadIdx.x < kD) {
            float bb = 0.f;
#pragma unroll 8
            for (int u = 0; u < kEE; u++) bb += eb[u] * w[u * kD + threadIdx.x];
            g_bep[layer * kD + threadIdx.x] = bb;
        }
    }
}

// ---------------- k2: single-block shuffle scan ------------------------------
__global__ void scan_single() {
    __shared__ int wtot[32];
    __shared__ int carrysh;
    int t = threadIdx.x, lane = t & 31, w = t >> 5;
    if (t == 0) carrysh = 0;
    __syncthreads();
    for (int c = 0; c < kSB; c++) {
        int n = c * 1024 + t;
        int v = (n < kN) ? g_deg[n] : 0;
        int inc = v;
#pragma unroll
        for (int o = 1; o < 32; o <<= 1) {
            int x = __shfl_up_sync(0xffffffffu, inc, o);
            if (lane >= o) inc += x;
        }
        if (lane == 31) wtot[w] = inc;
        __syncthreads();
        if (w == 0) {
            int wi = wtot[lane];
#pragma unroll
            for (int o = 1; o < 32; o <<= 1) {
                int y = __shfl_up_sync(0xffffffffu, wi, o);
                if (lane >= o) wi += y;
            }
            wtot[lane] = wi;
        }
        __syncthreads();
        int base = carrysh + (w ? wtot[w - 1] : 0);
        if (n < kN) g_off[n] = base + inc - v;
        __syncthreads();
        if (t == 0) carrysh += wtot[31];
        __syncthreads();
    }
    if (t == 0) g_off[kN] = carrysh;
}

// ---------------- xlr GEMM body ----------------------------------------------
__device__ __forceinline__ void xlr_body(const float* __restrict__ W,
                                         const float* __restrict__ bias,
                                         float* __restrict__ out, int n0,
                                         float* ws, float* xs) {
    int t = threadIdx.x;
    int lane = t & 31;
    int w = t >> 5;
    u64 acc[8][2] = {};
    for (int kt = 0; kt < kD; kt += 32) {
#pragma unroll
        for (int r = t; r < 32 * 128; r += 256)
            ws[r] = W[(kt + (r >> 7)) * kD + (r & 127)];
#pragma unroll
        for (int r = t; r < 64 * 32; r += 256) {
            int n = r >> 5, kk = r & 31;
            int nn = n0 + n;
            xs[kk * 68 + n] = (nn < kN) ? g_x[nn * kD + kt + kk] : 0.f;
        }
        __syncthreads();
#pragma unroll
        for (int kk = 0; kk < 32; kk++) {
            ulonglong2 wv = *(const ulonglong2*)&ws[kk * 128 + lane * 4];
            float4 xv0 = *(const float4*)&xs[kk * 68 + w * 8];
            float4 xv1 = *(const float4*)&xs[kk * 68 + w * 8 + 4];
            float xm[8] = {xv0.x, xv0.y, xv0.z, xv0.w, xv1.x, xv1.y, xv1.z, xv1.w};
#pragma unroll
            for (int m = 0; m < 8; m++) {
                u64 xp = splat2(xm[m]);
                acc[m][0] = fma2(xp, wv.x, acc[m][0]);
                acc[m][1] = fma2(xp, wv.y, acc[m][1]);
            }
        }
        __syncthreads();
    }
    float4 bv = *(const float4*)(bias + lane * 4);
#pragma unroll
    for (int m = 0; m < 8; m++) {
        int n = n0 + w * 8 + m;
        if (n < kN) {
            float a0, a1, a2, a3;
            unpack2(acc[m][0], a0, a1);
            unpack2(acc[m][1], a2, a3);
            float4 o = make_float4(a0 + bv.x, a1 + bv.y, a2 + bv.z, a3 + bv.w);
            *(float4*)&out[n * kD + lane * 4] = o;
        }
    }
}

// ---------------- k3: xlr layer0 + scatter_csr (grid split) -----------------
__global__ __launch_bounds__(256) void xlr_scatter(
        const float* __restrict__ Wl, const float* __restrict__ bl,
        const float* __restrict__ Wr, const float* __restrict__ br,
        const int* __restrict__ src, const int* __restrict__ dst,
        const float* __restrict__ eattr) {
    __shared__ __align__(16) float ws[32 * 128];
    __shared__ __align__(16) float xs[32 * 68];
    int b = blockIdx.x;
    if (b < kXlrB) {
        int half = b / (kXlrB / 2);
        int bx = b % (kXlrB / 2);
        const float* W = (half == 0 ? Wl : Wr);
        const float* bias = (half == 0 ? bl : br);
        float* out = half == 0 ? g_xl : g_xr;
        xlr_body(W, bias, out, bx * 64, ws, xs);
    } else {
        int e = (b - kXlrB) * 256 + threadIdx.x;
        if (e >= kE) return;
        int s = src[e], d = dst[e];
        if (s == d) return;
        int pos = atomicAdd(&g_cur[d], 1);
        int idx = g_off[d] + pos;
        g_csrc[idx] = s;
        float4 a = *(const float4*)&eattr[(size_t)e * 8];
        float4 bb = *(const float4*)&eattr[(size_t)e * 8 + 4];
        *(float4*)&g_eraw[(size_t)idx * 8] = a;
        *(float4*)&g_eraw[(size_t)idx * 8 + 4] = bb;
    }
}

// standalone xlr for layers 1-3
__global__ __launch_bounds__(256) void xlr_gemm(
        const float* __restrict__ Wl, const float* __restrict__ bl,
        const float* __restrict__ Wr, const float* __restrict__ br) {
    __shared__ __align__(16) float ws[32 * 128];
    __shared__ __align__(16) float xs[32 * 68];
    const float* W = (blockIdx.y == 0 ? Wl : Wr);
    const float* bias = (blockIdx.y == 0 ? bl : br);
    float* out = blockIdx.y == 0 ? g_xl : g_xr;
    xlr_body(W, bias, out, blockIdx.x * 64, ws, xs);
}

// ---------------- per-edge math ----------------------------------------------
__device__ __forceinline__ void egat_edge(
        float4 xls, float4 ra, float4 rb,
        const u64 (&Mr)[8][2], u64 xrb0, u64 xrb1, float4 attv, float lself,
        float& den, u64& acc0, u64& acc1) {
    u64 f0 = xrb0, f1 = xrb1;
    float rk[8] = {ra.x, ra.y, ra.z, ra.w, rb.x, rb.y, rb.z, rb.w};
#pragma unroll
    for (int k = 0; k < 8; k++) {
        u64 rp = splat2(rk[k]);
        f0 = fma2(rp, Mr[k][0], f0);
        f1 = fma2(rp, Mr[k][1], f1);
    }
    u64 xp0 = pack2(xls.x, xls.y), xp1 = pack2(xls.z, xls.w);
    f0 = add2(f0, xp0); f1 = add2(f1, xp1);
    float ax, ay, az, aw;
    unpack2(f0, ax, ay); unpack2(f1, az, aw);
    ax = fmaxf(ax, 0.2f * ax); ay = fmaxf(ay, 0.2f * ay);
    az = fmaxf(az, 0.2f * az); aw = fmaxf(aw, 0.2f * aw);
    float l2 = ax * attv.x + ay * attv.y + az * attv.z + aw * attv.w;
    l2 += __shfl_xor_sync(0xffffffffu, l2, 1);
    l2 += __shfl_xor_sync(0xffffffffu, l2, 2);
    float p = __expf(l2 - lself);
    den += p;
    u64 pp = splat2(p);
    acc0 = fma2(pp, xp0, acc0);
    acc1 = fma2(pp, xp1, acc1);
}

// ---------------- one node of the fused GAT layer ---------------------------
__device__ __forceinline__ void gat_node(
        int d, int layer, int lane, int j0, const u64 (&Mr)[8][2], float4 attv,
        const float* __restrict__ gbias, const float* __restrict__ gam,
        const float* __restrict__ bet) {
    float4 xld4 = *(const float4*)&g_xl[d * kD + j0];
    u64 xld0 = pack2(xld4.x, xld4.y), xld1 = pack2(xld4.z, xld4.w);

    int beg = g_off[d], end = g_off[d + 1];
    int cnt = end - beg;

    float a0, a1, a2, a3;
    if (cnt == 0) {
        a0 = xld4.x; a1 = xld4.y; a2 = xld4.z; a3 = xld4.w;
    } else {
        float4 bep4 = *(const float4*)&g_bep[layer * kD + j0];
        float4 xr4 = *(const float4*)&g_xr[d * kD + j0];
        u64 xrb0 = pack2(xr4.x + bep4.x, xr4.y + bep4.y);
        u64 xrb1 = pack2(xr4.z + bep4.z, xr4.w + bep4.w);

        // self-loop logit = fixed softmax shift (lraw holds SUM)
        float invc = 1.f / (float)cnt;
        float4 lr1 = *(const float4*)&g_lraw[d * 8];
        float4 lr2 = *(const float4*)&g_lraw[d * 8 + 4];
        u64 e0 = add2(xrb0, xld0), e1 = add2(xrb1, xld1);
        {
            float rk[8] = {lr1.x * invc, lr1.y * invc, lr1.z * invc, lr1.w * invc,
                           lr2.x * invc, lr2.y * invc, lr2.z * invc, lr2.w * invc};
#pragma unroll
            for (int k = 0; k < 8; k++) {
                u64 rp = splat2(rk[k]);
                e0 = fma2(rp, Mr[k][0], e0);
                e1 = fma2(rp, Mr[k][1], e1);
            }
        }
        float vx, vy, vz, vw;
        unpack2(e0, vx, vy); unpack2(e1, vz, vw);
        vx = fmaxf(vx, 0.2f * vx); vy = fmaxf(vy, 0.2f * vy);
        vz = fmaxf(vz, 0.2f * vz); vw = fmaxf(vw, 0.2f * vw);
        float lself = vx * attv.x + vy * attv.y + vz * attv.z + vw * attv.w;
        lself += __shfl_xor_sync(0xffffffffu, lself, 1);
        lself += __shfl_xor_sync(0xffffffffu, lself, 2);

        float den = 1.f;
        u64 acc0 = xld0, acc1 = xld1;

        int i = beg;
        if (cnt >= 4) {
            int sA0 = g_csrc[i], sA1 = g_csrc[i + 1];
            float4 xA0 = *(const float4*)&g_xl[(size_t)sA0 * kD + j0];
            float4 xA1 = *(const float4*)&g_xl[(size_t)sA1 * kD + j0];
            int sB0 = g_csrc[i + 2], sB1 = g_csrc[i + 3];
            float4 xB0, xB1;
            for (;;) {
                // phase A
                xB0 = *(const float4*)&g_xl[(size_t)sB0 * kD + j0];
                xB1 = *(const float4*)&g_xl[(size_t)sB1 * kD + j0];
                if (i + 5 < end) { sA0 = g_csrc[i + 4]; sA1 = g_csrc[i + 5]; }
                egat_edge(xA0, *(const float4*)&g_eraw[(size_t)i * 8],
                          *(const float4*)&g_eraw[(size_t)i * 8 + 4],
                          Mr, xrb0, xrb1, attv, lself, den, acc0, acc1);
                egat_edge(xA1, *(const float4*)&g_eraw[(size_t)(i + 1) * 8],
                          *(const float4*)&g_eraw[(size_t)(i + 1) * 8 + 4],
                          Mr, xrb0, xrb1, attv, lself, den, acc0, acc1);
                i += 2;
                if (i + 3 >= end) {
                    egat_edge(xB0, *(const float4*)&g_eraw[(size_t)i * 8],
                              *(const float4*)&g_eraw[(size_t)i * 8 + 4],
                              Mr, xrb0, xrb1, attv, lself, den, acc0, acc1);
                    egat_edge(xB1, *(const float4*)&g_eraw[(size_t)(i + 1) * 8],
                              *(const float4*)&g_eraw[(size_t)(i + 1) * 8 + 4],
                              Mr, xrb0, xrb1, attv, lself, den, acc0, acc1);
                    i += 2;
                    break;
                }
                // phase B
                xA0 = *(const float4*)&g_xl[(size_t)sA0 * kD + j0];
                xA1 = *(const float4*)&g_xl[(size_t)sA1 * kD + j0];
                if (i + 5 < end) { sB0 = g_csrc[i + 4]; sB1 = g_csrc[i + 5]; }
                egat_edge(xB0, *(const float4*)&g_eraw[(size_t)i * 8],
                          *(const float4*)&g_eraw[(size_t)i * 8 + 4],
                          Mr, xrb0, xrb1, attv, lself, den, acc0, acc1);
                egat_edge(xB1, *(const float4*)&g_eraw[(size_t)(i + 1) * 8],
                          *(const float4*)&g_eraw[(size_t)(i + 1) * 8 + 4],
                          Mr, xrb0, xrb1, attv, lself, den, acc0, acc1);
                i += 2;
                if (i + 3 >= end) {
                    egat_edge(xA0, *(const float4*)&g_eraw[(size_t)i * 8],
                              *(const float4*)&g_eraw[(size_t)i * 8 + 4],
                              Mr, xrb0, xrb1, attv, lself, den, acc0, acc1);
                    egat_edge(xA1, *(const float4*)&g_eraw[(size_t)(i + 1) * 8],
                              *(const float4*)&g_eraw[(size_t)(i + 1) * 8 + 4],
                              Mr, xrb0, xrb1, attv, lself, den, acc0, acc1);
                    i += 2;
                    break;
                }
            }
        }
        for (; i < end; i++) {
            int s = g_csrc[i];
            float4 xls = *(const float4*)&g_xl[(size_t)s * kD + j0];
            egat_edge(xls, *(const float4*)&g_eraw[(size_t)i * 8],
                      *(const float4*)&g_eraw[(size_t)i * 8 + 4],
                      Mr, xrb0, xrb1, attv, lself, den, acc0, acc1);
        }
        float inv = 1.f / den;
        float c0, c1, c2, c3;
        unpack2(acc0, c0, c1); unpack2(acc1, c2, c3);
        a0 = c0 * inv; a1 = c1 * inv; a2 = c2 * inv; a3 = c3 * inv;
    }

    float4 gb = __ldg((const float4*)&gbias[layer * kD + j0]);
    float4 gm = __ldg((const float4*)&gam[layer * kD + j0]);
    float4 bt = __ldg((const float4*)&bet[layer * kD + j0]);
    float w0 = gm.x * (a0 + gb.x) * kBNS + bt.x;
    float w1 = gm.y * (a1 + gb.y) * kBNS + bt.y;
    float w2 = gm.z * (a2 + gb.z) * kBNS + bt.z;
    float w3 = gm.w * (a3 + gb.w) * kBNS + bt.w;
    float4 o;
    o.x = w0 > 0.f ? w0 : expm1f(w0);
    o.y = w1 > 0.f ? w1 : expm1f(w1);
    o.z = w2 > 0.f ? w2 : expm1f(w2);
    o.w = w3 > 0.f ? w3 : expm1f(w3);
    *(float4*)&g_x[d * kD + j0] = o;
}

// ---------------- k4 (PROFILED): fused GAT, persistent work stealing --------
__global__ __launch_bounds__(128) void fused_gat(
        const float* __restrict__ att, const float* __restrict__ gbias,
        const float* __restrict__ gam, const float* __restrict__ bet, int layer) {
    int t = threadIdx.x, lane = t & 31;
    int j0 = lane * 4;

    u64 Mr[8][2];
#pragma unroll
    for (int k = 0; k < 8; k++) {
        float4 mv = *(const float4*)&g_M[layer * 8 * kD + k * kD + j0];
        Mr[k][0] = pack2(mv.x, mv.y);
        Mr[k][1] = pack2(mv.z, mv.w);
    }
    float4 attv = *(const float4*)&att[layer * kD + j0];

    int base = 0;
    if (lane == 0) base = atomicAdd(&g_work[layer], kChunk);
    base = __shfl_sync(0xffffffffu, base, 0);

    while (base < kN) {
        int nextBase = 0;
        if (lane == 0) nextBase = atomicAdd(&g_work[layer], kChunk);  // in flight
        int hi = min(base + kChunk, kN);
        for (int d = base; d < hi; d++)
            gat_node(d, layer, lane, j0, Mr, attv, gbias, gam, bet);
        base = __shfl_sync(0xffffffffu, nextBase, 0);   // atomic latency hidden
    }
}

// ---------------- pool + head + cleanup -------------------------------------
__global__ void pool(const int* __restrict__ batch) {
    int g = blockIdx.x;
    int t = threadIdx.x;   // 128
    __shared__ int slo, shi;
    if (t == 0) {
        int lo = 0, hi = kN;
        while (lo < hi) { int mid = (lo + hi) >> 1; if (batch[mid] < g) lo = mid + 1; else hi = mid; }
        slo = lo;
        hi = kN;
        while (lo < hi) { int mid = (lo + hi) >> 1; if (batch[mid] < g + 1) lo = mid + 1; else hi = mid; }
        shi = lo;
    }
    __syncthreads();
    int lo = slo, hi = shi;
    float s = 0.f;
    for (int n = lo; n < hi; n++) s += g_x[n * kD + t];
    g_gsum[g * kD + t] = s / fmaxf((float)(hi - lo), 1.f);
}

__global__ void head(const float* __restrict__ hW, const float* __restrict__ hb,
                     float* __restrict__ out) {
    int g = blockIdx.x;
    int lane = threadIdx.x;
    float acc[kNC] = {};
    for (int k = lane; k < kD; k += 32) {
        float mm = g_gsum[g * kD + k];
#pragma unroll
        for (int c = 0; c < kNC; c++) acc[c] += mm * hW[k * kNC + c];
    }
#pragma unroll
    for (int c = 0; c < kNC; c++) {
        float v = acc[c];
#pragma unroll
        for (int o = 16; o > 0; o >>= 1) v += __shfl_down_sync(0xffffffffu, v, o);
        if (lane == 0) out[g * kNC + c] = v + hb[c];
    }
}

__global__ void cleanup() {
    int i = blockIdx.x * blockDim.x + threadIdx.x;
    int stride = gridDim.x * blockDim.x;
    for (int t = i; t < kN; t += stride) { g_deg[t] = 0; g_cur[t] = 0; }
    for (int t = i; t < kN * 8; t += stride) g_lraw[t] = 0.f;
    if (i < kL) g_work[i] = 0;
}

// ---------------- launch -----------------------------------------------------
extern "C" void kernel_launch(void* const* d_in, const int* in_sizes, int n_in,
                              void* d_out, int out_size) {
    const int*   x_nodes = (const int*)d_in[0];
    const int*   esrc    = (const int*)d_in[1];
    const int*   edst    = (const int*)d_in[2];
    const float* eattr   = (const float*)d_in[3];
    const int*   batch   = (const int*)d_in[4];
    const float* nemb    = (const float*)d_in[5];
    const float* edge_W  = (const float*)d_in[6];
    const float* edge_b  = (const float*)d_in[7];
    const float* Wl      = (const float*)d_in[8];
    const float* bl      = (const float*)d_in[9];
    const float* Wr      = (const float*)d_in[10];
    const float* br      = (const float*)d_in[11];
    const float* We      = (const float*)d_in[12];
    const float* att     = (const float*)d_in[13];
    const float* gbias   = (const float*)d_in[14];
    const float* bng     = (const float*)d_in[15];
    const float* bnb     = (const float*)d_in[16];
    const float* headW   = (const float*)d_in[17];
    const float* headb   = (const float*)d_in[18];
    float* out = (float*)d_out;

    mega_prep<<<kEncB + kCntB + kL, 256>>>(x_nodes, nemb, esrc, edst, eattr,
                                           edge_W, edge_b, We);              // 1
    scan_single<<<1, 1024>>>();                                              // 2
    xlr_scatter<<<kXlrB + kScatB, 256>>>(Wl, bl, Wr, br, esrc, edst, eattr); // 3
    fused_gat<<<kGatB, 128>>>(att, gbias, bng, bnb, 0);                      // 4 (profiled)

    for (int i = 1; i < kL; i++) {
        xlr_gemm<<<dim3((kN + 63) / 64, 2), 256>>>(
            Wl + (size_t)i * kD * kD, bl + (size_t)i * kD,
            Wr + (size_t)i * kD * kD, br + (size_t)i * kD);
        fused_gat<<<kGatB, 128>>>(att, gbias, bng, bnb, i);
    }

    pool<<<kG, kD>>>(batch);
    head<<<kG, 32>>>(headW, headb, out);
    cleanup<<<512, 256>>>();
}

// round 12
// speedup vs baseline: 1.3444x; 1.0043x over previous
#include <cuda_runtime.h>
#include <math.h>

constexpr int kN   = 50000;
constexpr int kE   = 800000;
constexpr int kG   = 512;
constexpr int kD   = 128;
constexpr int kEE  = 64;
constexpr int kL   = 4;
constexpr int kNC  = 10;
constexpr int kSB  = (kN + 1023) / 1024;
constexpr float kBNS = 0.9999950000374997f;  // (1+1e-5)^-0.5

// grid split constants
constexpr int kEncB  = (kN * kD + 255) / 256;
constexpr int kCntB  = (kE * 8 + 255) / 256;
constexpr int kXlrB  = ((kN + 63) / 64) * 2;
constexpr int kScatB = (kE + 255) / 256;
constexpr int kGatB  = 888;          // 148 SMs x 6 resident blocks (80 regs, 128 thr)
constexpr int kChunk = 4;            // nodes per work-steal grab

typedef unsigned long long u64;

// ---------------- f32x2 packed helpers -------------------------------------
__device__ __forceinline__ u64 pack2(float lo, float hi) {
    u64 r; asm("mov.b64 %0,{%1,%2};" : "=l"(r) : "f"(lo), "f"(hi)); return r;
}
__device__ __forceinline__ u64 splat2(float v) { return pack2(v, v); }
__device__ __forceinline__ void unpack2(u64 p, float& lo, float& hi) {
    asm("mov.b64 {%0,%1},%2;" : "=f"(lo), "=f"(hi) : "l"(p));
}
__device__ __forceinline__ u64 fma2(u64 a, u64 b, u64 c) {
    u64 r; asm("fma.rn.f32x2 %0,%1,%2,%3;" : "=l"(r) : "l"(a), "l"(b), "l"(c)); return r;
}
__device__ __forceinline__ u64 add2(u64 a, u64 b) {
    u64 r; asm("add.rn.f32x2 %0,%1,%2;" : "=l"(r) : "l"(a), "l"(b)); return r;
}

// ---------------- scratch ----------------------------------------------------
__device__ float g_x[kN * kD];
__device__ float g_xl[kN * kD];
__device__ float g_xr[kN * kD];
__device__ float g_lraw[kN * 8];      // SUM of incoming raw attrs
__device__ int   g_deg[kN];
__device__ int   g_cur[kN];
__device__ int   g_off[kN + 1];
__device__ int   g_csrc[kE];
__device__ float g_eraw[(size_t)kE * 8];
__device__ float g_M[kL * 8 * kD];
__device__ float g_bep[kL * kD];
__device__ float g_gsum[kG * kD];
__device__ int   g_work[kL];          // per-layer work-steal counters (.bss zero)

// ---------------- k1: node_encode + degree/lraw atomics + make_M ------------
__global__ void mega_prep(const int* __restrict__ xn, const float* __restrict__ emb,
                          const int* __restrict__ src, const int* __restrict__ dst,
                          const float* __restrict__ eattr,
                          const float* __restrict__ eW, const float* __restrict__ eb,
                          const float* __restrict__ We) {
    int b = blockIdx.x;
    if (b < kEncB) {
        int t = b * 256 + threadIdx.x;
        if (t < kN * kD) {
            int n = t >> 7, j = t & 127;
            g_x[t] = emb[xn[n] * kD + j];
        }
    } else if (b < kEncB + kCntB) {
        int t = (b - kEncB) * 256 + threadIdx.x;
        if (t < kE * 8) {
            int e = t >> 3, j = t & 7;
            int s = src[e], d = dst[e];
            if (s != d) {
                atomicAdd(&g_lraw[d * 8 + j], eattr[t]);
                if (j == 0) atomicAdd(&g_deg[d], 1);
            }
        }
    } else {
        int layer = b - kEncB - kCntB;
        const float* w = We + (size_t)layer * kEE * kD;
        for (int r = threadIdx.x; r < 8 * kD; r += 256) {
            int k = r >> 7, j = r & 127;
            float acc = 0.f;
#pragma unroll 8
            for (int u = 0; u < kEE; u++) acc += eW[k * kEE + u] * w[u * kD + j];
            g_M[layer * 8 * kD + r] = acc;
        }
        if (threadIdx.x < kD) {
            float bb = 0.f;
#pragma unroll 8
            for (int u = 0; u < kEE; u++) bb += eb[u] * w[u * kD + threadIdx.x];
            g_bep[layer * kD + threadIdx.x] = bb;
        }
    }
}

// ---------------- k2: single-block shuffle scan ------------------------------
__global__ void scan_single() {
    __shared__ int wtot[32];
    __shared__ int carrysh;
    int t = threadIdx.x, lane = t & 31, w = t >> 5;
    if (t == 0) carrysh = 0;
    __syncthreads();
    for (int c = 0; c < kSB; c++) {
        int n = c * 1024 + t;
        int v = (n < kN) ? g_deg[n] : 0;
        int inc = v;
#pragma unroll
        for (int o = 1; o < 32; o <<= 1) {
            int x = __shfl_up_sync(0xffffffffu, inc, o);
            if (lane >= o) inc += x;
        }
        if (lane == 31) wtot[w] = inc;
        __syncthreads();
        if (w == 0) {
            int wi = wtot[lane];
#pragma unroll
            for (int o = 1; o < 32; o <<= 1) {
                int y = __shfl_up_sync(0xffffffffu, wi, o);
                if (lane >= o) wi += y;
            }
            wtot[lane] = wi;
        }
        __syncthreads();
        int base = carrysh + (w ? wtot[w - 1] : 0);
        if (n < kN) g_off[n] = base + inc - v;
        __syncthreads();
        if (t == 0) carrysh += wtot[31];
        __syncthreads();
    }
    if (t == 0) g_off[kN] = carrysh;
}

// ---------------- xlr GEMM body ----------------------------------------------
__device__ __forceinline__ void xlr_body(const float* __restrict__ W,
                                         const float* __restrict__ bias,
                                         float* __restrict__ out, int n0,
                                         float* ws, float* xs) {
    int t = threadIdx.x;
    int lane = t & 31;
    int w = t >> 5;
    u64 acc[8][2] = {};
    for (int kt = 0; kt < kD; kt += 32) {
#pragma unroll
        for (int r = t; r < 32 * 128; r += 256)
            ws[r] = W[(kt + (r >> 7)) * kD + (r & 127)];
#pragma unroll
        for (int r = t; r < 64 * 32; r += 256) {
            int n = r >> 5, kk = r & 31;
            int nn = n0 + n;
            xs[kk * 68 + n] = (nn < kN) ? g_x[nn * kD + kt + kk] : 0.f;
        }
        __syncthreads();
#pragma unroll
        for (int kk = 0; kk < 32; kk++) {
            ulonglong2 wv = *(const ulonglong2*)&ws[kk * 128 + lane * 4];
            float4 xv0 = *(const float4*)&xs[kk * 68 + w * 8];
            float4 xv1 = *(const float4*)&xs[kk * 68 + w * 8 + 4];
            float xm[8] = {xv0.x, xv0.y, xv0.z, xv0.w, xv1.x, xv1.y, xv1.z, xv1.w};
#pragma unroll
            for (int m = 0; m < 8; m++) {
                u64 xp = splat2(xm[m]);
                acc[m][0] = fma2(xp, wv.x, acc[m][0]);
                acc[m][1] = fma2(xp, wv.y, acc[m][1]);
            }
        }
        __syncthreads();
    }
    float4 bv = *(const float4*)(bias + lane * 4);
#pragma unroll
    for (int m = 0; m < 8; m++) {
        int n = n0 + w * 8 + m;
        if (n < kN) {
            float a0, a1, a2, a3;
            unpack2(acc[m][0], a0, a1);
            unpack2(acc[m][1], a2, a3);
            float4 o = make_float4(a0 + bv.x, a1 + bv.y, a2 + bv.z, a3 + bv.w);
            *(float4*)&out[n * kD + lane * 4] = o;
        }
    }
}

// ---------------- k3: xlr layer0 + scatter_csr (grid split) -----------------
__global__ __launch_bounds__(256) void xlr_scatter(
        const float* __restrict__ Wl, const float* __restrict__ bl,
        const float* __restrict__ Wr, const float* __restrict__ br,
        const int* __restrict__ src, const int* __restrict__ dst,
        const float* __restrict__ eattr) {
    __shared__ __align__(16) float ws[32 * 128];
    __shared__ __align__(16) float xs[32 * 68];
    int b = blockIdx.x;
    if (b < kXlrB) {
        int half = b / (kXlrB / 2);
        int bx = b % (kXlrB / 2);
        const float* W = (half == 0 ? Wl : Wr);
        const float* bias = (half == 0 ? bl : br);
        float* out = half == 0 ? g_xl : g_xr;
        xlr_body(W, bias, out, bx * 64, ws, xs);
    } else {
        int e = (b - kXlrB) * 256 + threadIdx.x;
        if (e >= kE) return;
        int s = src[e], d = dst[e];
        if (s == d) return;
        int pos = atomicAdd(&g_cur[d], 1);
        int idx = g_off[d] + pos;
        g_csrc[idx] = s;
        float4 a = *(const float4*)&eattr[(size_t)e * 8];
        float4 bb = *(const float4*)&eattr[(size_t)e * 8 + 4];
        *(float4*)&g_eraw[(size_t)idx * 8] = a;
        *(float4*)&g_eraw[(size_t)idx * 8 + 4] = bb;
    }
}

// standalone xlr for layers 1-3
__global__ __launch_bounds__(256) void xlr_gemm(
        const float* __restrict__ Wl, const float* __restrict__ bl,
        const float* __restrict__ Wr, const float* __restrict__ br) {
    __shared__ __align__(16) float ws[32 * 128];
    __shared__ __align__(16) float xs[32 * 68];
    const float* W = (blockIdx.y == 0 ? Wl : Wr);
    const float* bias = (blockIdx.y == 0 ? bl : br);
    float* out = blockIdx.y == 0 ? g_xl : g_xr;
    xlr_body(W, bias, out, blockIdx.x * 64, ws, xs);
}

// ---------------- per-edge math ----------------------------------------------
__device__ __forceinline__ void egat_edge(
        float4 xls, float4 ra, float4 rb,
        const u64 (&Mr)[8][2], u64 xrb0, u64 xrb1, float4 attv, float lself,
        float& den, u64& acc0, u64& acc1) {
    u64 f0 = xrb0, f1 = xrb1;
    float rk[8] = {ra.x, ra.y, ra.z, ra.w, rb.x, rb.y, rb.z, rb.w};
#pragma unroll
    for (int k = 0; k < 8; k++) {
        u64 rp = splat2(rk[k]);
        f0 = fma2(rp, Mr[k][0], f0);
        f1 = fma2(rp, Mr[k][1], f1);
    }
    u64 xp0 = pack2(xls.x, xls.y), xp1 = pack2(xls.z, xls.w);
    f0 = add2(f0, xp0); f1 = add2(f1, xp1);
    float ax, ay, az, aw;
    unpack2(f0, ax, ay); unpack2(f1, az, aw);
    ax = fmaxf(ax, 0.2f * ax); ay = fmaxf(ay, 0.2f * ay);
    az = fmaxf(az, 0.2f * az); aw = fmaxf(aw, 0.2f * aw);
    float l2 = ax * attv.x + ay * attv.y + az * attv.z + aw * attv.w;
    l2 += __shfl_xor_sync(0xffffffffu, l2, 1);
    l2 += __shfl_xor_sync(0xffffffffu, l2, 2);
    float p = __expf(l2 - lself);
    den += p;
    u64 pp = splat2(p);
    acc0 = fma2(pp, xp0, acc0);
    acc1 = fma2(pp, xp1, acc1);
}

// ---------------- one node of the fused GAT layer ---------------------------
__device__ __forceinline__ void gat_node(
        int d, int layer, int lane, int j0, const u64 (&Mr)[8][2], float4 attv,
        const float* __restrict__ gbias, const float* __restrict__ gam,
        const float* __restrict__ bet) {
    float4 xld4 = *(const float4*)&g_xl[d * kD + j0];
    u64 xld0 = pack2(xld4.x, xld4.y), xld1 = pack2(xld4.z, xld4.w);

    int beg = g_off[d], end = g_off[d + 1];
    int cnt = end - beg;

    float a0, a1, a2, a3;
    if (cnt == 0) {
        a0 = xld4.x; a1 = xld4.y; a2 = xld4.z; a3 = xld4.w;
    } else {
        float4 bep4 = *(const float4*)&g_bep[layer * kD + j0];
        float4 xr4 = *(const float4*)&g_xr[d * kD + j0];
        u64 xrb0 = pack2(xr4.x + bep4.x, xr4.y + bep4.y);
        u64 xrb1 = pack2(xr4.z + bep4.z, xr4.w + bep4.w);

        // self-loop logit = fixed softmax shift (lraw holds SUM)
        float invc = 1.f / (float)cnt;
        float4 lr1 = *(const float4*)&g_lraw[d * 8];
        float4 lr2 = *(const float4*)&g_lraw[d * 8 + 4];
        u64 e0 = add2(xrb0, xld0), e1 = add2(xrb1, xld1);
        {
            float rk[8] = {lr1.x * invc, lr1.y * invc, lr1.z * invc, lr1.w * invc,
                           lr2.x * invc, lr2.y * invc, lr2.z * invc, lr2.w * invc};
#pragma unroll
            for (int k = 0; k < 8; k++) {
                u64 rp = splat2(rk[k]);
                e0 = fma2(rp, Mr[k][0], e0);
                e1 = fma2(rp, Mr[k][1], e1);
            }
        }
        float vx, vy, vz, vw;
        unpack2(e0, vx, vy); unpack2(e1, vz, vw);
        vx = fmaxf(vx, 0.2f * vx); vy = fmaxf(vy, 0.2f * vy);
        vz = fmaxf(vz, 0.2f * vz); vw = fmaxf(vw, 0.2f * vw);
        float lself = vx * attv.x + vy * attv.y + vz * attv.z + vw * attv.w;
        lself += __shfl_xor_sync(0xffffffffu, lself, 1);
        lself += __shfl_xor_sync(0xffffffffu, lself, 2);

        float den = 1.f;
        u64 acc0 = xld0, acc1 = xld1;

        int i = beg;
        if (cnt >= 4) {
            int sA0 = g_csrc[i], sA1 = g_csrc[i + 1];
            float4 xA0 = *(const float4*)&g_xl[(size_t)sA0 * kD + j0];
            float4 xA1 = *(const float4*)&g_xl[(size_t)sA1 * kD + j0];
            int sB0 = g_csrc[i + 2], sB1 = g_csrc[i + 3];
            float4 xB0, xB1;
            for (;;) {
                // phase A
                xB0 = *(const float4*)&g_xl[(size_t)sB0 * kD + j0];
                xB1 = *(const float4*)&g_xl[(size_t)sB1 * kD + j0];
                if (i + 5 < end) { sA0 = g_csrc[i + 4]; sA1 = g_csrc[i + 5]; }
                egat_edge(xA0, *(const float4*)&g_eraw[(size_t)i * 8],
                          *(const float4*)&g_eraw[(size_t)i * 8 + 4],
                          Mr, xrb0, xrb1, attv, lself, den, acc0, acc1);
                egat_edge(xA1, *(const float4*)&g_eraw[(size_t)(i + 1) * 8],
                          *(const float4*)&g_eraw[(size_t)(i + 1) * 8 + 4],
                          Mr, xrb0, xrb1, attv, lself, den, acc0, acc1);
                i += 2;
                if (i + 3 >= end) {
                    egat_edge(xB0, *(const float4*)&g_eraw[(size_t)i * 8],
                              *(const float4*)&g_eraw[(size_t)i * 8 + 4],
                              Mr, xrb0, xrb1, attv, lself, den, acc0, acc1);
                    egat_edge(xB1, *(const float4*)&g_eraw[(size_t)(i + 1) * 8],
                              *(const float4*)&g_eraw[(size_t)(i + 1) * 8 + 4],
                              Mr, xrb0, xrb1, attv, lself, den, acc0, acc1);
                    i += 2;
                    break;
                }
                // phase B
                xA0 = *(const float4*)&g_xl[(size_t)sA0 * kD + j0];
                xA1 = *(const float4*)&g_xl[(size_t)sA1 * kD + j0];
                if (i + 5 < end) { sB0 = g_csrc[i + 4]; sB1 = g_csrc[i + 5]; }
                egat_edge(xB0, *(const float4*)&g_eraw[(size_t)i * 8],
                          *(const float4*)&g_eraw[(size_t)i * 8 + 4],
                          Mr, xrb0, xrb1, attv, lself, den, acc0, acc1);
                egat_edge(xB1, *(const float4*)&g_eraw[(size_t)(i + 1) * 8],
                          *(const float4*)&g_eraw[(size_t)(i + 1) * 8 + 4],
                          Mr, xrb0, xrb1, attv, lself, den, acc0, acc1);
                i += 2;
                if (i + 3 >= end) {
                    egat_edge(xA0, *(const float4*)&g_eraw[(size_t)i * 8],
                              *(const float4*)&g_eraw[(size_t)i * 8 + 4],
                              Mr, xrb0, xrb1, attv, lself, den, acc0, acc1);
                    egat_edge(xA1, *(const float4*)&g_eraw[(size_t)(i + 1) * 8],
                              *(const float4*)&g_eraw[(size_t)(i + 1) * 8 + 4],
                              Mr, xrb0, xrb1, attv, lself, den, acc0, acc1);
                    i += 2;
                    break;
                }
            }
        }
        for (; i < end; i++) {
            int s = g_csrc[i];
            float4 xls = *(const float4*)&g_xl[(size_t)s * kD + j0];
            egat_edge(xls, *(const float4*)&g_eraw[(size_t)i * 8],
                      *(const float4*)&g_eraw[(size_t)i * 8 + 4],
                      Mr, xrb0, xrb1, attv, lself, den, acc0, acc1);
        }
        float inv = 1.f / den;
        float c0, c1, c2, c3;
        unpack2(acc0, c0, c1); unpack2(acc1, c2, c3);
        a0 = c0 * inv; a1 = c1 * inv; a2 = c2 * inv; a3 = c3 * inv;
    }

    float4 gb = __ldg((const float4*)&gbias[layer * kD + j0]);
    float4 gm = __ldg((const float4*)&gam[layer * kD + j0]);
    float4 bt = __ldg((const float4*)&bet[layer * kD + j0]);
    float w0 = gm.x * (a0 + gb.x) * kBNS + bt.x;
    float w1 = gm.y * (a1 + gb.y) * kBNS + bt.y;
    float w2 = gm.z * (a2 + gb.z) * kBNS + bt.z;
    float w3 = gm.w * (a3 + gb.w) * kBNS + bt.w;
    float4 o;
    o.x = w0 > 0.f ? w0 : expm1f(w0);
    o.y = w1 > 0.f ? w1 : expm1f(w1);
    o.z = w2 > 0.f ? w2 : expm1f(w2);
    o.w = w3 > 0.f ? w3 : expm1f(w3);
    *(float4*)&g_x[d * kD + j0] = o;
}

// ---------------- k4 (PROFILED): fused GAT, persistent, 6 blocks/SM ---------
__global__ __launch_bounds__(128, 6) void fused_gat(
        const float* __restrict__ att, const float* __restrict__ gbias,
        const float* __restrict__ gam, const float* __restrict__ bet, int layer) {
    int t = threadIdx.x, lane = t & 31;
    int j0 = lane * 4;

    u64 Mr[8][2];
#pragma unroll
    for (int k = 0; k < 8; k++) {
        float4 mv = *(const float4*)&g_M[layer * 8 * kD + k * kD + j0];
        Mr[k][0] = pack2(mv.x, mv.y);
        Mr[k][1] = pack2(mv.z, mv.w);
    }
    float4 attv = *(const float4*)&att[layer * kD + j0];

    int base = 0;
    if (lane == 0) base = atomicAdd(&g_work[layer], kChunk);
    base = __shfl_sync(0xffffffffu, base, 0);

    while (base < kN) {
        int nextBase = 0;
        if (lane == 0) nextBase = atomicAdd(&g_work[layer], kChunk);  // in flight
        int hi = min(base + kChunk, kN);
        for (int d = base; d < hi; d++)
            gat_node(d, layer, lane, j0, Mr, attv, gbias, gam, bet);
        base = __shfl_sync(0xffffffffu, nextBase, 0);   // atomic latency hidden
    }
}

// ---------------- pool + head + cleanup -------------------------------------
__global__ void pool(const int* __restrict__ batch) {
    int g = blockIdx.x;
    int t = threadIdx.x;   // 128
    __shared__ int slo, shi;
    if (t == 0) {
        int lo = 0, hi = kN;
        while (lo < hi) { int mid = (lo + hi) >> 1; if (batch[mid] < g) lo = mid + 1; else hi = mid; }
        slo = lo;
        hi = kN;
        while (lo < hi) { int mid = (lo + hi) >> 1; if (batch[mid] < g + 1) lo = mid + 1; else hi = mid; }
        shi = lo;
    }
    __syncthreads();
    int lo = slo, hi = shi;
    float s = 0.f;
    for (int n = lo; n < hi; n++) s += g_x[n * kD + t];
    g_gsum[g * kD + t] = s / fmaxf((float)(hi - lo), 1.f);
}

__global__ void head(const float* __restrict__ hW, const float* __restrict__ hb,
                     float* __restrict__ out) {
    int g = blockIdx.x;
    int lane = threadIdx.x;
    float acc[kNC] = {};
    for (int k = lane; k < kD; k += 32) {
        float mm = g_gsum[g * kD + k];
#pragma unroll
        for (int c = 0; c < kNC; c++) acc[c] += mm * hW[k * kNC + c];
    }
#pragma unroll
    for (int c = 0; c < kNC; c++) {
        float v = acc[c];
#pragma unroll
        for (int o = 16; o > 0; o >>= 1) v += __shfl_down_sync(0xffffffffu, v, o);
        if (lane == 0) out[g * kNC + c] = v + hb[c];
    }
}

__global__ void cleanup() {
    int i = blockIdx.x * blockDim.x + threadIdx.x;
    int stride = gridDim.x * blockDim.x;
    for (int t = i; t < kN; t += stride) { g_deg[t] = 0; g_cur[t] = 0; }
    for (int t = i; t < kN * 8; t += stride) g_lraw[t] = 0.f;
    if (i < kL) g_work[i] = 0;
}

// ---------------- launch -----------------------------------------------------
extern "C" void kernel_launch(void* const* d_in, const int* in_sizes, int n_in,
                              void* d_out, int out_size) {
    const int*   x_nodes = (const int*)d_in[0];
    const int*   esrc    = (const int*)d_in[1];
    const int*   edst    = (const int*)d_in[2];
    const float* eattr   = (const float*)d_in[3];
    const int*   batch   = (const int*)d_in[4];
    const float* nemb    = (const float*)d_in[5];
    const float* edge_W  = (const float*)d_in[6];
    const float* edge_b  = (const float*)d_in[7];
    const float* Wl      = (const float*)d_in[8];
    const float* bl      = (const float*)d_in[9];
    const float* Wr      = (const float*)d_in[10];
    const float* br      = (const float*)d_in[11];
    const float* We      = (const float*)d_in[12];
    const float* att     = (const float*)d_in[13];
    const float* gbias   = (const float*)d_in[14];
    const float* bng     = (const float*)d_in[15];
    const float* bnb     = (const float*)d_in[16];
    const float* headW   = (const float*)d_in[17];
    const float* headb   = (const float*)d_in[18];
    float* out = (float*)d_out;

    mega_prep<<<kEncB + kCntB + kL, 256>>>(x_nodes, nemb, esrc, edst, eattr,
                                           edge_W, edge_b, We);              // 1
    scan_single<<<1, 1024>>>();                                              // 2
    xlr_scatter<<<kXlrB + kScatB, 256>>>(Wl, bl, Wr, br, esrc, edst, eattr); // 3
    fused_gat<<<kGatB, 128>>>(att, gbias, bng, bnb, 0);                      // 4 (profiled)

    for (int i = 1; i < kL; i++) {
        xlr_gemm<<<dim3((kN + 63) / 64, 2), 256>>>(
            Wl + (size_t)i * kD * kD, bl + (size_t)i * kD,
            Wr + (size_t)i * kD * kD, br + (size_t)i * kD);
        fused_gat<<<kGatB, 128>>>(att, gbias, bng, bnb, i);
    }

    pool<<<kG, kD>>>(batch);
    head<<<kG, 32>>>(headW, headb, out);
    cleanup<<<512, 256>>>();
}